// round 14
// baseline (speedup 1.0000x reference)
#include <cuda_runtime.h>
#include <cuda_fp16.h>
#include <cstdint>

#define N_USER 100000
#define N_BIZ  50000
#define NEDGE  500000
#define D_IN   256
#define D_H    512
#define D_OUT  256

#define NBLK_U 98
#define NBLK_B 49
#define NBLK_TOT (NBLK_U + NBLK_B)

// ---------------- scratch (static device globals) ----------------------------
__device__ __half g_xh_user[(size_t)N_USER * D_IN];
__device__ __half g_xh_biz[(size_t)N_BIZ * D_IN];
__device__ __half g_mean_b1[(size_t)N_BIZ * D_IN];
__device__ __half g_mean_u1[(size_t)N_USER * D_IN];
__device__ __half g_h_biz[(size_t)N_BIZ * D_H];
__device__ __half g_h_user[(size_t)N_USER * D_H];
__device__ __half g_mean_b2[(size_t)N_BIZ * D_H];
__device__ __half g_y[(size_t)N_BIZ * D_OUT];
__device__ __half g_mean_y[(size_t)N_USER * D_OUT];
__device__ __half g_wt[8 * 131072];
__device__ float g_inv_biz[N_BIZ];
__device__ float g_inv_user[N_USER];
__device__ int g_cnt_user[N_USER];
__device__ int g_cnt_biz[N_BIZ];
__device__ int g_off_user[N_USER + 1];
__device__ int g_off_biz[N_BIZ + 1];
__device__ int g_cur_user[N_USER];
__device__ int g_cur_biz[N_BIZ];
__device__ int g_adj_user[NEDGE];
__device__ int g_adj_biz[NEDGE];
__device__ int g_bsum[NBLK_TOT];

// ---------------- helpers ----------------------------------------------------
static __device__ __forceinline__ void cp16(void* sdst, const void* gsrc, bool pred) {
    uint32_t s;
    asm("{ .reg .u64 t; cvta.to.shared.u64 t, %1; cvt.u32.u64 %0, t; }"
        : "=r"(s) : "l"(sdst));
    const int sz = pred ? 16 : 0;
    asm volatile("cp.async.cg.shared.global [%0], [%1], 16, %2;"
                 :: "r"(s), "l"(gsrc), "r"(sz) : "memory");
}
#define LDSM_X4(r0, r1, r2, r3, addr)                                           \
    asm volatile("ldmatrix.sync.aligned.m8n8.x4.shared.b16 {%0,%1,%2,%3}, [%4];" \
                 : "=r"(r0), "=r"(r1), "=r"(r2), "=r"(r3) : "r"(addr))
#define MMA_F16(d, a0, a1, a2, a3, b0, b1)                                      \
    asm volatile("mma.sync.aligned.m16n8k16.row.col.f32.f16.f16.f32 "           \
                 "{%0,%1,%2,%3}, {%4,%5,%6,%7}, {%8,%9}, {%0,%1,%2,%3};"        \
                 : "+f"((d)[0]), "+f"((d)[1]), "+f"((d)[2]), "+f"((d)[3])       \
                 : "r"(a0), "r"(a1), "r"(a2), "r"(a3), "r"(b0), "r"(b1))

// ---------------- fused prep + transpose (one launch) ------------------------
struct TransProbs { const float* W[8]; };

__global__ void prep_trans_kernel(const float4* __restrict__ xu,
                                  const float4* __restrict__ xb,
                                  __half2* __restrict__ xhu, __half2* __restrict__ xhb,
                                  int* __restrict__ cnt_u, int* __restrict__ cnt_b,
                                  TransProbs tp, __half* __restrict__ wt,
                                  int prepBlocks) {
    __shared__ float tbuf[32][33];
    if ((int)blockIdx.x < prepBlocks) {
        const int n4u = N_USER * D_IN / 4, n4b = N_BIZ * D_IN / 4;
        int i = blockIdx.x * 256 + threadIdx.x;
        if (i < n4u) {
            float4 v = __ldg(xu + i);
            xhu[i * 2] = __floats2half2_rn(v.x, v.y);
            xhu[i * 2 + 1] = __floats2half2_rn(v.z, v.w);
        } else if (i < n4u + n4b) {
            int j = i - n4u;
            float4 v = __ldg(xb + j);
            xhb[j * 2] = __floats2half2_rn(v.x, v.y);
            xhb[j * 2 + 1] = __floats2half2_rn(v.z, v.w);
        }
        if (i < N_USER) cnt_u[i] = 0;
        if (i < N_BIZ) cnt_b[i] = 0;
    } else {
        const int t = blockIdx.x - prepBlocks;   // 0..1023 (128 tiles x 8 mats)
        const int m = t >> 7;
        const int rem = t & 127;
        const int K = (m < 4) ? D_IN : D_H;
        const int N = (m < 4) ? D_H : D_OUT;
        const int ntiles = N / 32;
        const int n0 = (rem % ntiles) * 32;
        const int k0 = (rem / ntiles) * 32;
        const float* __restrict__ W = tp.W[m];
        __half* __restrict__ Wt = wt + (size_t)m * 131072;
        const int tx = threadIdx.x & 31, ty = threadIdx.x >> 5;   // ty 0..7
#pragma unroll
        for (int i = 0; i < 4; i++)
            tbuf[ty + i * 8][tx] = W[(size_t)(k0 + ty + i * 8) * N + n0 + tx];
        __syncthreads();
#pragma unroll
        for (int i = 0; i < 4; i++)
            Wt[(size_t)(n0 + ty + i * 8) * K + k0 + tx] =
                __float2half_rn(tbuf[tx][ty + i * 8]);
    }
}

// ---------------- CSR build --------------------------------------------------
__global__ void hist_kernel(const int* __restrict__ e_src,
                            const int* __restrict__ e_dst,
                            int* __restrict__ cnt_u, int* __restrict__ cnt_b, int E) {
    int i = blockIdx.x * blockDim.x + threadIdx.x;
    if (i < E) {
        atomicAdd(&cnt_u[e_src[i]], 1);
        atomicAdd(&cnt_b[e_dst[i]], 1);
    }
}

__global__ void scanA_kernel(const int* __restrict__ cnt_u,
                             const int* __restrict__ cnt_b,
                             int* __restrict__ bsum) {
    __shared__ int ws[32];
    const int b = blockIdx.x, tid = threadIdx.x;
    const int lane = tid & 31, wid = tid >> 5;
    const int* cnt = (b < NBLK_U) ? cnt_u : cnt_b;
    const int n = (b < NBLK_U) ? N_USER : N_BIZ;
    const int base = ((b < NBLK_U) ? b : b - NBLK_U) * 1024;
    const int i = base + tid;
    int v = (i < n) ? cnt[i] : 0;
#pragma unroll
    for (int s = 16; s > 0; s >>= 1) v += __shfl_down_sync(0xFFFFFFFFu, v, s);
    if (lane == 0) ws[wid] = v;
    __syncthreads();
    if (wid == 0) {
        int w = ws[lane];
#pragma unroll
        for (int s = 16; s > 0; s >>= 1) w += __shfl_down_sync(0xFFFFFFFFu, w, s);
        if (lane == 0) bsum[b] = w;
    }
}

// scanC with inlined carry computation (replaces scanB)
__global__ void scanC_kernel(const int* __restrict__ cnt_u,
                             const int* __restrict__ cnt_b,
                             const int* __restrict__ bsum,
                             int* __restrict__ off_u, int* __restrict__ cur_u,
                             float* __restrict__ inv_u,
                             int* __restrict__ off_b, int* __restrict__ cur_b,
                             float* __restrict__ inv_b) {
    __shared__ int ws[32];
    __shared__ int carry_s;
    const int b = blockIdx.x, tid = threadIdx.x;
    const int lane = tid & 31, wid = tid >> 5;
    const bool isU = (b < NBLK_U);

    // carry = sum of bsum over this segment's blocks before b
    {
        int contrib = 0;
        if (tid < NBLK_TOT) {
            const bool in = isU ? (tid < b) : (tid >= NBLK_U && tid < b);
            if (in) contrib = bsum[tid];
        }
        int v = contrib;
#pragma unroll
        for (int s = 16; s > 0; s >>= 1) v += __shfl_down_sync(0xFFFFFFFFu, v, s);
        if (lane == 0) ws[wid] = v;
        __syncthreads();
        if (wid == 0) {
            int w = ws[lane];
#pragma unroll
            for (int s = 16; s > 0; s >>= 1) w += __shfl_down_sync(0xFFFFFFFFu, w, s);
            if (lane == 0) carry_s = w;
        }
        __syncthreads();
    }
    const int carry = carry_s;
    __syncthreads();   // ws reuse barrier

    const int* cnt = isU ? cnt_u : cnt_b;
    int* off = isU ? off_u : off_b;
    int* cur = isU ? cur_u : cur_b;
    float* inv = isU ? inv_u : inv_b;
    const int n = isU ? N_USER : N_BIZ;
    const int base = (isU ? b : b - NBLK_U) * 1024;
    const int i = base + tid;
    const int v = (i < n) ? cnt[i] : 0;
    int x = v;
#pragma unroll
    for (int s = 1; s < 32; s <<= 1) {
        int y = __shfl_up_sync(0xFFFFFFFFu, x, s);
        if (lane >= s) x += y;
    }
    if (lane == 31) ws[wid] = x;
    __syncthreads();
    if (wid == 0) {
        int w = ws[lane];
#pragma unroll
        for (int s = 1; s < 32; s <<= 1) {
            int y = __shfl_up_sync(0xFFFFFFFFu, w, s);
            if (lane >= s) w += y;
        }
        ws[lane] = w;
    }
    __syncthreads();
    const int woff = (wid == 0) ? 0 : ws[wid - 1];
    const int excl = carry + woff + x - v;
    if (i < n) {
        off[i] = excl; cur[i] = excl;
        inv[i] = 1.0f / fmaxf((float)v, 1.0f);
        if (i == n - 1) off[n] = excl + v;
    }
}

__global__ void fill_kernel(const int* __restrict__ e_src,
                            const int* __restrict__ e_dst,
                            int* __restrict__ cur_u, int* __restrict__ cur_b,
                            int* __restrict__ adj_u, int* __restrict__ adj_b, int E) {
    int i = blockIdx.x * blockDim.x + threadIdx.x;
    if (i < E) {
        const int s = e_src[i], d = e_dst[i];
        adj_b[atomicAdd(&cur_b[d], 1)] = s;
        adj_u[atomicAdd(&cur_u[s], 1)] = d;
    }
}

// ---------------- gather-mean row worker (fp16 in/out, fp32 acc, MLP=4) ------
struct GatherProb {
    const uint4* feat; const int* off; const int* adj; const float* inv;
    uint4* out; int d8; int nrows; int nblk;
};

static __device__ __forceinline__ void gather_row(const GatherProb& p, int n, int tid) {
    const int d8 = p.d8;
    const int s = __ldg(p.off + n), e = __ldg(p.off + n + 1);
    float2 a[4][4];
#pragma unroll
    for (int u = 0; u < 4; u++)
#pragma unroll
        for (int j = 0; j < 4; j++) a[u][j] = make_float2(0.f, 0.f);
    int i = s;
    for (; i + 3 < e; i += 4) {
        const int s0 = __ldg(p.adj + i),     s1 = __ldg(p.adj + i + 1);
        const int s2 = __ldg(p.adj + i + 2), s3 = __ldg(p.adj + i + 3);
        const uint4 v0 = __ldg(p.feat + (size_t)s0 * d8 + tid);
        const uint4 v1 = __ldg(p.feat + (size_t)s1 * d8 + tid);
        const uint4 v2 = __ldg(p.feat + (size_t)s2 * d8 + tid);
        const uint4 v3 = __ldg(p.feat + (size_t)s3 * d8 + tid);
        const __half2* h0 = (const __half2*)&v0;
        const __half2* h1 = (const __half2*)&v1;
        const __half2* h2 = (const __half2*)&v2;
        const __half2* h3 = (const __half2*)&v3;
#pragma unroll
        for (int j = 0; j < 4; j++) {
            float2 f0 = __half22float2(h0[j]); a[0][j].x += f0.x; a[0][j].y += f0.y;
            float2 f1 = __half22float2(h1[j]); a[1][j].x += f1.x; a[1][j].y += f1.y;
            float2 f2 = __half22float2(h2[j]); a[2][j].x += f2.x; a[2][j].y += f2.y;
            float2 f3 = __half22float2(h3[j]); a[3][j].x += f3.x; a[3][j].y += f3.y;
        }
    }
    for (; i < e; ++i) {
        const int s0 = __ldg(p.adj + i);
        const uint4 v0 = __ldg(p.feat + (size_t)s0 * d8 + tid);
        const __half2* h0 = (const __half2*)&v0;
#pragma unroll
        for (int j = 0; j < 4; j++) {
            float2 f0 = __half22float2(h0[j]);
            a[0][j].x += f0.x; a[0][j].y += f0.y;
        }
    }
    const float sc = __ldg(p.inv + n);
    uint4 o;
    __half2* oh = (__half2*)&o;
#pragma unroll
    for (int j = 0; j < 4; j++) {
        float ox = ((a[0][j].x + a[1][j].x) + (a[2][j].x + a[3][j].x)) * sc;
        float oy = ((a[0][j].y + a[1][j].y) + (a[2][j].y + a[3][j].y)) * sc;
        oh[j] = __floats2half2_rn(ox, oy);
    }
    p.out[(size_t)n * d8 + tid] = o;
}

// dual-problem gather, 64 threads/block
__global__ void gather2_kernel(GatherProb p0, GatherProb p1) {
    const bool first = (blockIdx.x < (unsigned)p0.nblk);
    const GatherProb p = first ? p0 : p1;
    const int lb = first ? blockIdx.x : blockIdx.x - p0.nblk;
    const int rpb = 64 / p.d8;
    const int n = lb * rpb + (int)(threadIdx.x / p.d8);
    if (n >= p.nrows) return;
    gather_row(p, n, (int)threadIdx.x & (p.d8 - 1));
}

// ---------------- fp16 mma.sync GEMM tile (device fn) ------------------------
#define SMH_STRIDE 40
#define SMH_MAT    (128 * SMH_STRIDE)
#define SMH_BUF    (2 * SMH_MAT)
#define N_STAGE    3
#define SMEM_BYTES (N_STAGE * SMH_BUF * 2)   // 61440 B

struct GProb {
    const __half* A; const __half* X; const __half* Wtl; const __half* Wtr;
    const float* bias; const __half* add; void* out;
    int M, K, N, npass, out_half, ytiles;
};

static __device__ __forceinline__ void gemm_tile(const GProb& p, int bm, int bn,
                                                 __half* sm, uint32_t smb) {
    const int tid = threadIdx.x, lane = tid & 31, wid = tid >> 5;
    const int wm = wid >> 2, wn = wid & 3;
    const int g = lane >> 2, t4 = lane & 3;

    const int srow = tid >> 1;
    const int sq = (tid & 1) * 16;
    const int grow = bm + srow;
    const bool rok = grow < p.M;

    const __half* arow[2];
    arow[0] = p.A + (size_t)(rok ? grow : 0) * p.K;
    arow[1] = p.X + (size_t)(rok ? grow : 0) * p.K;
    const __half* brow[2];
    brow[0] = p.Wtl + (size_t)(bn + srow) * p.K;
    brow[1] = p.Wtr + (size_t)(bn + srow) * p.K;

    const int CH = p.K >> 5;
    const int T = p.npass * CH;

    const int lr = lane & 7, lmi = lane >> 3;
    const uint32_t aoff = (uint32_t)(((wm * 64 + (lmi & 1) * 8 + lr) * SMH_STRIDE
                                      + (lmi >> 1) * 8) * 2);
    const uint32_t boff = (uint32_t)(((wn * 32 + (lmi >> 1) * 8 + lr) * SMH_STRIDE
                                      + (lmi & 1) * 8) * 2);

    float acc[4][4][4];
#pragma unroll
    for (int i = 0; i < 4; i++)
#pragma unroll
        for (int j = 0; j < 4; j++)
#pragma unroll
            for (int r = 0; r < 4; r++) acc[i][j][r] = 0.0f;

    auto stage = [&](int cc, int buf) {
        const int pass = (cc >= CH) ? 1 : 0;
        const int k0 = (cc - pass * CH) << 5;
        __half* As = sm + buf * SMH_BUF;
        __half* Bs = As + SMH_MAT;
        const __half* ap = arow[pass] + k0 + sq;
        const __half* bp = brow[pass] + k0 + sq;
        const int so = srow * SMH_STRIDE + sq;
        cp16(As + so, ap, rok);
        cp16(As + so + 8, ap + 8, rok);
        cp16(Bs + so, bp, true);
        cp16(Bs + so + 8, bp + 8, true);
    };

    auto compute = [&](int buf) {
        const uint32_t aS = smb + (uint32_t)(buf * SMH_BUF * 2);
        const uint32_t bS = aS + SMH_MAT * 2;
#pragma unroll
        for (int ks = 0; ks < 2; ++ks) {
            const uint32_t kbb = ks * 32;
            uint32_t bfr[4][2];
#pragma unroll
            for (int ntp = 0; ntp < 2; ++ntp) {
                uint32_t r0, r1, r2, r3;
                LDSM_X4(r0, r1, r2, r3,
                        bS + boff + (uint32_t)(ntp * 16 * SMH_STRIDE * 2) + kbb);
                bfr[2 * ntp][0] = r0; bfr[2 * ntp][1] = r1;
                bfr[2 * ntp + 1][0] = r2; bfr[2 * ntp + 1][1] = r3;
            }
#pragma unroll
            for (int mt = 0; mt < 4; ++mt) {
                uint32_t a0, a1, a2, a3;
                LDSM_X4(a0, a1, a2, a3,
                        aS + aoff + (uint32_t)(mt * 16 * SMH_STRIDE * 2) + kbb);
#pragma unroll
                for (int nt = 0; nt < 4; ++nt)
                    MMA_F16(acc[mt][nt], a0, a1, a2, a3, bfr[nt][0], bfr[nt][1]);
            }
        }
    };

    stage(0, 0);
    asm volatile("cp.async.commit_group;" ::: "memory");
    stage(1, 1);
    asm volatile("cp.async.commit_group;" ::: "memory");

#pragma unroll 1
    for (int cc = 0; cc < T; ++cc) {
        asm volatile("cp.async.wait_group %0;" :: "n"(1) : "memory");
        __syncthreads();
        if (cc + 2 < T) stage(cc + 2, (cc + 2) % N_STAGE);
        asm volatile("cp.async.commit_group;" ::: "memory");
        compute(cc % N_STAGE);
    }

#pragma unroll
    for (int mt = 0; mt < 4; ++mt) {
#pragma unroll
        for (int rr = 0; rr < 2; ++rr) {
            const int r = bm + wm * 64 + mt * 16 + g + rr * 8;
            if (r < p.M) {
                const int cb = bn + wn * 32;
#pragma unroll
                for (int nt = 0; nt < 4; ++nt) {
                    const int c = nt * 8 + t4 * 2;
                    float ox = acc[mt][nt][rr * 2 + 0];
                    float oy = acc[mt][nt][rr * 2 + 1];
                    if (p.add) {
                        __half2 av = *(const __half2*)(p.add + (size_t)r * p.N + cb + c);
                        float2 af = __half22float2(av);
                        ox += af.x; oy += af.y;
                    }
                    if (p.bias) {
                        ox = fmaxf(ox + p.bias[cb + c], 0.f);
                        oy = fmaxf(oy + p.bias[cb + c + 1], 0.f);
                    }
                    if (p.out_half) {
                        *(__half2*)((__half*)p.out + (size_t)r * p.N + cb + c) =
                            __floats2half2_rn(ox, oy);
                    } else {
                        *(float2*)((float*)p.out + (size_t)r * p.N + cb + c) =
                            make_float2(ox, oy);
                    }
                }
            }
        }
    }
}

__global__ void __launch_bounds__(256, 2)
sage_mma_batched(GProb q0, GProb q1) {
    extern __shared__ __half sm[];
    uint32_t smb;
    asm("{ .reg .u64 t; cvta.to.shared.u64 t, %1; cvt.u32.u64 %0, t; }"
        : "=r"(smb) : "l"(sm));
    const GProb p = (blockIdx.z == 0) ? q0 : q1;
    if ((int)blockIdx.y >= p.ytiles) return;
    gemm_tile(p, blockIdx.y * 128, blockIdx.x * 128, sm, smb);
}

// heterogeneous: GEMM blocks + gather blocks in one launch (pipe overlap)
__global__ void __launch_bounds__(256, 2)
ygemm_gather_kernel(GProb q, GatherProb gp, int gemmBlocks, int ntiles) {
    extern __shared__ __half sm[];
    if ((int)blockIdx.x < gemmBlocks) {
        uint32_t smb;
        asm("{ .reg .u64 t; cvta.to.shared.u64 t, %1; cvt.u32.u64 %0, t; }"
            : "=r"(smb) : "l"(sm));
        const int bn = ((int)blockIdx.x % ntiles) * 128;
        const int bm = ((int)blockIdx.x / ntiles) * 128;
        gemm_tile(q, bm, bn, sm, smb);
    } else {
        const int rpb = 256 / gp.d8;
        const int n = ((int)blockIdx.x - gemmBlocks) * rpb + (int)threadIdx.x / gp.d8;
        if (n < gp.nrows)
            gather_row(gp, n, (int)threadIdx.x & (gp.d8 - 1));
    }
}

// ---------------- launch (single stream, 10 launches) ------------------------
extern "C" void kernel_launch(void* const* d_in, const int* in_sizes, int n_in,
                              void* d_out, int out_size) {
    const float* x_user = (const float*)d_in[0];
    const float* x_biz  = (const float*)d_in[1];
    const int* e_src = (const int*)d_in[2];
    const int* e_dst = (const int*)d_in[3];
    const float* b1_ub   = (const float*)d_in[6];
    const float* b1_bu   = (const float*)d_in[9];
    const float* b2_ub   = (const float*)d_in[12];
    const float* b2_bu   = (const float*)d_in[15];

    float* o_user = (float*)d_out;
    float* o_biz  = (float*)d_out + (size_t)N_USER * D_OUT;

    __half *xh_u, *xh_b, *mean_b1, *mean_u1, *h_biz, *h_user, *mean_b2, *y, *mean_y, *wt;
    float *inv_b, *inv_u;
    int *cnt_u, *cnt_b, *off_u, *off_b, *cur_u, *cur_b, *adj_u, *adj_b, *bsum;
    cudaGetSymbolAddress((void**)&xh_u,    g_xh_user);
    cudaGetSymbolAddress((void**)&xh_b,    g_xh_biz);
    cudaGetSymbolAddress((void**)&mean_b1, g_mean_b1);
    cudaGetSymbolAddress((void**)&mean_u1, g_mean_u1);
    cudaGetSymbolAddress((void**)&h_biz,   g_h_biz);
    cudaGetSymbolAddress((void**)&h_user,  g_h_user);
    cudaGetSymbolAddress((void**)&mean_b2, g_mean_b2);
    cudaGetSymbolAddress((void**)&y,       g_y);
    cudaGetSymbolAddress((void**)&mean_y,  g_mean_y);
    cudaGetSymbolAddress((void**)&wt,      g_wt);
    cudaGetSymbolAddress((void**)&inv_b,   g_inv_biz);
    cudaGetSymbolAddress((void**)&inv_u,   g_inv_user);
    cudaGetSymbolAddress((void**)&cnt_u,   g_cnt_user);
    cudaGetSymbolAddress((void**)&cnt_b,   g_cnt_biz);
    cudaGetSymbolAddress((void**)&off_u,   g_off_user);
    cudaGetSymbolAddress((void**)&off_b,   g_off_biz);
    cudaGetSymbolAddress((void**)&cur_u,   g_cur_user);
    cudaGetSymbolAddress((void**)&cur_b,   g_cur_biz);
    cudaGetSymbolAddress((void**)&adj_u,   g_adj_user);
    cudaGetSymbolAddress((void**)&adj_b,   g_adj_biz);
    cudaGetSymbolAddress((void**)&bsum,    g_bsum);

    cudaGetLastError();
    cudaFuncSetAttribute(sage_mma_batched,
                         cudaFuncAttributeMaxDynamicSharedMemorySize, SMEM_BYTES);
    cudaFuncSetAttribute(ygemm_gather_kernel,
                         cudaFuncAttributeMaxDynamicSharedMemorySize, SMEM_BYTES);

    // (1) prep (fp16 round + zero counters) + 8 weight transposes, one launch
    {
        const int prepBlocks = (N_USER * D_IN / 4 + N_BIZ * D_IN / 4 + 255) / 256;
        TransProbs tp;
        tp.W[0] = (const float*)d_in[4];  tp.W[1] = (const float*)d_in[5];
        tp.W[2] = (const float*)d_in[7];  tp.W[3] = (const float*)d_in[8];
        tp.W[4] = (const float*)d_in[10]; tp.W[5] = (const float*)d_in[11];
        tp.W[6] = (const float*)d_in[13]; tp.W[7] = (const float*)d_in[14];
        prep_trans_kernel<<<prepBlocks + 1024, 256>>>(
            (const float4*)x_user, (const float4*)x_biz,
            (__half2*)xh_u, (__half2*)xh_b, cnt_u, cnt_b, tp, wt, prepBlocks);
    }
    // (2-5) CSR build
    hist_kernel<<<(NEDGE + 255) / 256, 256>>>(e_src, e_dst, cnt_u, cnt_b, NEDGE);
    scanA_kernel<<<NBLK_TOT, 1024>>>(cnt_u, cnt_b, bsum);
    scanC_kernel<<<NBLK_TOT, 1024>>>(cnt_u, cnt_b, bsum, off_u, cur_u, inv_u,
                                     off_b, cur_b, inv_b);
    fill_kernel<<<(NEDGE + 255) / 256, 256>>>(e_src, e_dst, cur_u, cur_b,
                                              adj_u, adj_b, NEDGE);

    // (6) L1 gathers fused: mean_b1 + mean_u1
    {
        GatherProb p0{(const uint4*)xh_u, off_b, adj_b, inv_b, (uint4*)mean_b1,
                      D_IN / 8, N_BIZ, (N_BIZ + 1) / 2};
        GatherProb p1{(const uint4*)xh_b, off_u, adj_u, inv_u, (uint4*)mean_u1,
                      D_IN / 8, N_USER, (N_USER + 1) / 2};
        gather2_kernel<<<p0.nblk + p1.nblk, 64>>>(p0, p1);
    }

    // (7) L1 GEMMs batched: h_biz + h_user
    {
        GProb q0{mean_b1, xh_b, wt + 0 * 131072, wt + 1 * 131072, b1_ub, nullptr,
                 h_biz, N_BIZ, D_IN, D_H, 2, 1, (N_BIZ + 127) / 128};
        GProb q1{mean_u1, xh_u, wt + 2 * 131072, wt + 3 * 131072, b1_bu, nullptr,
                 h_user, N_USER, D_IN, D_H, 2, 1, (N_USER + 127) / 128};
        dim3 grd(D_H / 128, (N_USER + 127) / 128, 2);
        sage_mma_batched<<<grd, 256, SMEM_BYTES>>>(q0, q1);
    }

    // (8) heterogeneous: y = h_biz @ W2_l_bu (tensor) || gather mean_b2 (memory)
    {
        GProb q{h_biz, h_biz, wt + 6 * 131072, wt + 6 * 131072, nullptr, nullptr,
                y, N_BIZ, D_H, D_OUT, 1, 1, (N_BIZ + 127) / 128};
        const int ntiles = D_OUT / 128;                       // 2
        const int gemmBlocks = ntiles * ((N_BIZ + 127) / 128); // 782
        GatherProb gp{(const uint4*)h_user, off_b, adj_b, inv_b, (uint4*)mean_b2,
                      D_H / 8, N_BIZ, 0};
        const int rpb = 256 / (D_H / 8);                      // 4 rows / 256-thr block
        const int gatherBlocks = (N_BIZ + rpb - 1) / rpb;     // 12500
        ygemm_gather_kernel<<<gemmBlocks + gatherBlocks, 256, SMEM_BYTES>>>(
            q, gp, gemmBlocks, ntiles);
    }

    // (9) gather mean_y (from y, d8=32)
    {
        GatherProb p0{(const uint4*)y, off_u, adj_u, inv_u, (uint4*)mean_y,
                      D_OUT / 8, N_USER, (N_USER + 1) / 2};
        GatherProb p1 = p0; p1.nblk = 0; p1.nrows = 0;
        gather2_kernel<<<p0.nblk, 64>>>(p0, p1);
    }

    // (10) final GEMMs batched: o_biz + o_user
    {
        GProb q0{mean_b2, h_biz, wt + 4 * 131072, wt + 5 * 131072, b2_ub, nullptr,
                 o_biz, N_BIZ, D_H, D_OUT, 2, 0, (N_BIZ + 127) / 128};
        GProb q1{h_user, h_user, wt + 7 * 131072, wt + 7 * 131072, b2_bu, mean_y,
                 o_user, N_USER, D_H, D_OUT, 1, 0, (N_USER + 127) / 128};
        dim3 grd(D_OUT / 128, (N_USER + 127) / 128, 2);
        sage_mma_batched<<<grd, 256, SMEM_BYTES>>>(q0, q1);
    }
}

// round 15
// speedup vs baseline: 1.0731x; 1.0731x over previous
#include <cuda_runtime.h>
#include <cuda_fp16.h>
#include <cstdint>

#define N_USER 100000
#define N_BIZ  50000
#define NEDGE  500000
#define D_IN   256
#define D_H    512
#define D_OUT  256

#define NBLK_U 98
#define NBLK_B 49
#define NBLK_TOT (NBLK_U + NBLK_B)

// ---------------- scratch (static device globals) ----------------------------
__device__ __half g_xh_user[(size_t)N_USER * D_IN];
__device__ __half g_xh_biz[(size_t)N_BIZ * D_IN];
__device__ __half g_mean_b1[(size_t)N_BIZ * D_IN];
__device__ __half g_mean_u1[(size_t)N_USER * D_IN];
__device__ __half g_h_biz[(size_t)N_BIZ * D_H];
__device__ __half g_h_user[(size_t)N_USER * D_H];
__device__ __half g_mean_b2[(size_t)N_BIZ * D_H];
__device__ __half g_y[(size_t)N_BIZ * D_OUT];
__device__ __half g_mean_y[(size_t)N_USER * D_OUT];
__device__ __half g_wt[8 * 131072];
__device__ float g_inv_biz[N_BIZ];
__device__ float g_inv_user[N_USER];
__device__ int g_cnt_user[N_USER];
__device__ int g_cnt_biz[N_BIZ];
__device__ int g_off_user[N_USER + 1];
__device__ int g_off_biz[N_BIZ + 1];
__device__ int g_cur_user[N_USER];
__device__ int g_cur_biz[N_BIZ];
__device__ int g_adj_user[NEDGE];
__device__ int g_adj_biz[NEDGE];
__device__ int g_bsum[NBLK_TOT];

// ---------------- helpers ----------------------------------------------------
static __device__ __forceinline__ void cp16(void* sdst, const void* gsrc, bool pred) {
    uint32_t s;
    asm("{ .reg .u64 t; cvta.to.shared.u64 t, %1; cvt.u32.u64 %0, t; }"
        : "=r"(s) : "l"(sdst));
    const int sz = pred ? 16 : 0;
    asm volatile("cp.async.cg.shared.global [%0], [%1], 16, %2;"
                 :: "r"(s), "l"(gsrc), "r"(sz) : "memory");
}
#define LDSM_X4(r0, r1, r2, r3, addr)                                           \
    asm volatile("ldmatrix.sync.aligned.m8n8.x4.shared.b16 {%0,%1,%2,%3}, [%4];" \
                 : "=r"(r0), "=r"(r1), "=r"(r2), "=r"(r3) : "r"(addr))
#define MMA_F16(d, a0, a1, a2, a3, b0, b1)                                      \
    asm volatile("mma.sync.aligned.m16n8k16.row.col.f32.f16.f16.f32 "           \
                 "{%0,%1,%2,%3}, {%4,%5,%6,%7}, {%8,%9}, {%0,%1,%2,%3};"        \
                 : "+f"((d)[0]), "+f"((d)[1]), "+f"((d)[2]), "+f"((d)[3])       \
                 : "r"(a0), "r"(a1), "r"(a2), "r"(a3), "r"(b0), "r"(b1))

// ---------------- fused prep + transpose (one launch) ------------------------
struct TransProbs { const float* W[8]; };

__global__ void prep_trans_kernel(const float4* __restrict__ xu,
                                  const float4* __restrict__ xb,
                                  __half2* __restrict__ xhu, __half2* __restrict__ xhb,
                                  int* __restrict__ cnt_u, int* __restrict__ cnt_b,
                                  TransProbs tp, __half* __restrict__ wt,
                                  int prepBlocks) {
    __shared__ float tbuf[32][33];
    if ((int)blockIdx.x < prepBlocks) {
        const int n4u = N_USER * D_IN / 4, n4b = N_BIZ * D_IN / 4;
        int i = blockIdx.x * 256 + threadIdx.x;
        if (i < n4u) {
            float4 v = __ldg(xu + i);
            xhu[i * 2] = __floats2half2_rn(v.x, v.y);
            xhu[i * 2 + 1] = __floats2half2_rn(v.z, v.w);
        } else if (i < n4u + n4b) {
            int j = i - n4u;
            float4 v = __ldg(xb + j);
            xhb[j * 2] = __floats2half2_rn(v.x, v.y);
            xhb[j * 2 + 1] = __floats2half2_rn(v.z, v.w);
        }
        if (i < N_USER) cnt_u[i] = 0;
        if (i < N_BIZ) cnt_b[i] = 0;
    } else {
        const int t = blockIdx.x - prepBlocks;   // 0..1023 (128 tiles x 8 mats)
        const int m = t >> 7;
        const int rem = t & 127;
        const int K = (m < 4) ? D_IN : D_H;
        const int N = (m < 4) ? D_H : D_OUT;
        const int ntiles = N / 32;
        const int n0 = (rem % ntiles) * 32;
        const int k0 = (rem / ntiles) * 32;
        const float* __restrict__ W = tp.W[m];
        __half* __restrict__ Wt = wt + (size_t)m * 131072;
        const int tx = threadIdx.x & 31, ty = threadIdx.x >> 5;   // ty 0..7
#pragma unroll
        for (int i = 0; i < 4; i++)
            tbuf[ty + i * 8][tx] = W[(size_t)(k0 + ty + i * 8) * N + n0 + tx];
        __syncthreads();
#pragma unroll
        for (int i = 0; i < 4; i++)
            Wt[(size_t)(n0 + ty + i * 8) * K + k0 + tx] =
                __float2half_rn(tbuf[tx][ty + i * 8]);
    }
}

// ---------------- CSR build --------------------------------------------------
__global__ void hist_kernel(const int* __restrict__ e_src,
                            const int* __restrict__ e_dst,
                            int* __restrict__ cnt_u, int* __restrict__ cnt_b, int E) {
    int i = blockIdx.x * blockDim.x + threadIdx.x;
    if (i < E) {
        atomicAdd(&cnt_u[e_src[i]], 1);
        atomicAdd(&cnt_b[e_dst[i]], 1);
    }
}

__global__ void scanA_kernel(const int* __restrict__ cnt_u,
                             const int* __restrict__ cnt_b,
                             int* __restrict__ bsum) {
    __shared__ int ws[32];
    const int b = blockIdx.x, tid = threadIdx.x;
    const int lane = tid & 31, wid = tid >> 5;
    const int* cnt = (b < NBLK_U) ? cnt_u : cnt_b;
    const int n = (b < NBLK_U) ? N_USER : N_BIZ;
    const int base = ((b < NBLK_U) ? b : b - NBLK_U) * 1024;
    const int i = base + tid;
    int v = (i < n) ? cnt[i] : 0;
#pragma unroll
    for (int s = 16; s > 0; s >>= 1) v += __shfl_down_sync(0xFFFFFFFFu, v, s);
    if (lane == 0) ws[wid] = v;
    __syncthreads();
    if (wid == 0) {
        int w = ws[lane];
#pragma unroll
        for (int s = 16; s > 0; s >>= 1) w += __shfl_down_sync(0xFFFFFFFFu, w, s);
        if (lane == 0) bsum[b] = w;
    }
}

// scanC with inlined carry computation (replaces scanB)
__global__ void scanC_kernel(const int* __restrict__ cnt_u,
                             const int* __restrict__ cnt_b,
                             const int* __restrict__ bsum,
                             int* __restrict__ off_u, int* __restrict__ cur_u,
                             float* __restrict__ inv_u,
                             int* __restrict__ off_b, int* __restrict__ cur_b,
                             float* __restrict__ inv_b) {
    __shared__ int ws[32];
    __shared__ int carry_s;
    const int b = blockIdx.x, tid = threadIdx.x;
    const int lane = tid & 31, wid = tid >> 5;
    const bool isU = (b < NBLK_U);

    // carry = sum of bsum over this segment's blocks before b
    {
        int contrib = 0;
        if (tid < NBLK_TOT) {
            const bool in = isU ? (tid < b) : (tid >= NBLK_U && tid < b);
            if (in) contrib = bsum[tid];
        }
        int v = contrib;
#pragma unroll
        for (int s = 16; s > 0; s >>= 1) v += __shfl_down_sync(0xFFFFFFFFu, v, s);
        if (lane == 0) ws[wid] = v;
        __syncthreads();
        if (wid == 0) {
            int w = ws[lane];
#pragma unroll
            for (int s = 16; s > 0; s >>= 1) w += __shfl_down_sync(0xFFFFFFFFu, w, s);
            if (lane == 0) carry_s = w;
        }
        __syncthreads();
    }
    const int carry = carry_s;
    __syncthreads();   // ws reuse barrier

    const int* cnt = isU ? cnt_u : cnt_b;
    int* off = isU ? off_u : off_b;
    int* cur = isU ? cur_u : cur_b;
    float* inv = isU ? inv_u : inv_b;
    const int n = isU ? N_USER : N_BIZ;
    const int base = (isU ? b : b - NBLK_U) * 1024;
    const int i = base + tid;
    const int v = (i < n) ? cnt[i] : 0;
    int x = v;
#pragma unroll
    for (int s = 1; s < 32; s <<= 1) {
        int y = __shfl_up_sync(0xFFFFFFFFu, x, s);
        if (lane >= s) x += y;
    }
    if (lane == 31) ws[wid] = x;
    __syncthreads();
    if (wid == 0) {
        int w = ws[lane];
#pragma unroll
        for (int s = 1; s < 32; s <<= 1) {
            int y = __shfl_up_sync(0xFFFFFFFFu, w, s);
            if (lane >= s) w += y;
        }
        ws[lane] = w;
    }
    __syncthreads();
    const int woff = (wid == 0) ? 0 : ws[wid - 1];
    const int excl = carry + woff + x - v;
    if (i < n) {
        off[i] = excl; cur[i] = excl;
        inv[i] = 1.0f / fmaxf((float)v, 1.0f);
        if (i == n - 1) off[n] = excl + v;
    }
}

__global__ void fill_kernel(const int* __restrict__ e_src,
                            const int* __restrict__ e_dst,
                            int* __restrict__ cur_u, int* __restrict__ cur_b,
                            int* __restrict__ adj_u, int* __restrict__ adj_b, int E) {
    int i = blockIdx.x * blockDim.x + threadIdx.x;
    if (i < E) {
        const int s = e_src[i], d = e_dst[i];
        adj_b[atomicAdd(&cur_b[d], 1)] = s;
        adj_u[atomicAdd(&cur_u[s], 1)] = d;
    }
}

// ------- dual gather-mean (64-thread blocks, zero smem, MLP=4) ---------------
struct GatherProb {
    const uint4* feat; const int* off; const int* adj; const float* inv;
    uint4* out; int d8; int nrows; int nblk;
};

static __device__ __forceinline__ void gather_row(const GatherProb& p, int n, int tid) {
    const int d8 = p.d8;
    const int s = __ldg(p.off + n), e = __ldg(p.off + n + 1);
    float2 a[4][4];
#pragma unroll
    for (int u = 0; u < 4; u++)
#pragma unroll
        for (int j = 0; j < 4; j++) a[u][j] = make_float2(0.f, 0.f);
    int i = s;
    for (; i + 3 < e; i += 4) {
        const int s0 = __ldg(p.adj + i),     s1 = __ldg(p.adj + i + 1);
        const int s2 = __ldg(p.adj + i + 2), s3 = __ldg(p.adj + i + 3);
        const uint4 v0 = __ldg(p.feat + (size_t)s0 * d8 + tid);
        const uint4 v1 = __ldg(p.feat + (size_t)s1 * d8 + tid);
        const uint4 v2 = __ldg(p.feat + (size_t)s2 * d8 + tid);
        const uint4 v3 = __ldg(p.feat + (size_t)s3 * d8 + tid);
        const __half2* h0 = (const __half2*)&v0;
        const __half2* h1 = (const __half2*)&v1;
        const __half2* h2 = (const __half2*)&v2;
        const __half2* h3 = (const __half2*)&v3;
#pragma unroll
        for (int j = 0; j < 4; j++) {
            float2 f0 = __half22float2(h0[j]); a[0][j].x += f0.x; a[0][j].y += f0.y;
            float2 f1 = __half22float2(h1[j]); a[1][j].x += f1.x; a[1][j].y += f1.y;
            float2 f2 = __half22float2(h2[j]); a[2][j].x += f2.x; a[2][j].y += f2.y;
            float2 f3 = __half22float2(h3[j]); a[3][j].x += f3.x; a[3][j].y += f3.y;
        }
    }
    for (; i < e; ++i) {
        const int s0 = __ldg(p.adj + i);
        const uint4 v0 = __ldg(p.feat + (size_t)s0 * d8 + tid);
        const __half2* h0 = (const __half2*)&v0;
#pragma unroll
        for (int j = 0; j < 4; j++) {
            float2 f0 = __half22float2(h0[j]);
            a[0][j].x += f0.x; a[0][j].y += f0.y;
        }
    }
    const float sc = __ldg(p.inv + n);
    uint4 o;
    __half2* oh = (__half2*)&o;
#pragma unroll
    for (int j = 0; j < 4; j++) {
        float ox = ((a[0][j].x + a[1][j].x) + (a[2][j].x + a[3][j].x)) * sc;
        float oy = ((a[0][j].y + a[1][j].y) + (a[2][j].y + a[3][j].y)) * sc;
        oh[j] = __floats2half2_rn(ox, oy);
    }
    p.out[(size_t)n * d8 + tid] = o;
}

__global__ void gather2_kernel(GatherProb p0, GatherProb p1) {
    const bool first = (blockIdx.x < (unsigned)p0.nblk);
    const GatherProb p = first ? p0 : p1;
    const int lb = first ? blockIdx.x : blockIdx.x - p0.nblk;
    const int rpb = 64 / p.d8;
    const int n = lb * rpb + (int)(threadIdx.x / p.d8);
    if (n >= p.nrows) return;
    gather_row(p, n, (int)threadIdx.x & (p.d8 - 1));
}

// ---------------- fp16 mma.sync SAGE GEMM (batched 2-problem) ----------------
#define SMH_STRIDE 40
#define SMH_MAT    (128 * SMH_STRIDE)
#define SMH_BUF    (2 * SMH_MAT)
#define N_STAGE    3
#define SMEM_BYTES (N_STAGE * SMH_BUF * 2)   // 61440 B

struct GProb {
    const __half* A; const __half* X; const __half* Wtl; const __half* Wtr;
    const float* bias; const __half* add; void* out;
    int M, K, N, npass, out_half, ytiles;
};

__global__ void __launch_bounds__(256, 2)
sage_mma_batched(GProb q0, GProb q1) {
    const GProb p = (blockIdx.z == 0) ? q0 : q1;
    if ((int)blockIdx.y >= p.ytiles) return;

    extern __shared__ __half sm[];
    uint32_t smb;
    asm("{ .reg .u64 t; cvta.to.shared.u64 t, %1; cvt.u32.u64 %0, t; }"
        : "=r"(smb) : "l"(sm));
    const int tid = threadIdx.x, lane = tid & 31, wid = tid >> 5;
    const int wm = wid >> 2, wn = wid & 3;
    const int g = lane >> 2, t4 = lane & 3;

    const int bm = blockIdx.y * 128, bn = blockIdx.x * 128;
    const int srow = tid >> 1;
    const int sq = (tid & 1) * 16;
    const int grow = bm + srow;
    const bool rok = grow < p.M;

    const __half* arow[2];
    arow[0] = p.A + (size_t)(rok ? grow : 0) * p.K;
    arow[1] = p.X + (size_t)(rok ? grow : 0) * p.K;
    const __half* brow[2];
    brow[0] = p.Wtl + (size_t)(bn + srow) * p.K;
    brow[1] = p.Wtr + (size_t)(bn + srow) * p.K;

    const int CH = p.K >> 5;
    const int T = p.npass * CH;

    const int lr = lane & 7, lmi = lane >> 3;
    const uint32_t aoff = (uint32_t)(((wm * 64 + (lmi & 1) * 8 + lr) * SMH_STRIDE
                                      + (lmi >> 1) * 8) * 2);
    const uint32_t boff = (uint32_t)(((wn * 32 + (lmi >> 1) * 8 + lr) * SMH_STRIDE
                                      + (lmi & 1) * 8) * 2);

    float acc[4][4][4];
#pragma unroll
    for (int i = 0; i < 4; i++)
#pragma unroll
        for (int j = 0; j < 4; j++)
#pragma unroll
            for (int r = 0; r < 4; r++) acc[i][j][r] = 0.0f;

    auto stage = [&](int cc, int buf) {
        const int pass = (cc >= CH) ? 1 : 0;
        const int k0 = (cc - pass * CH) << 5;
        __half* As = sm + buf * SMH_BUF;
        __half* Bs = As + SMH_MAT;
        const __half* ap = arow[pass] + k0 + sq;
        const __half* bp = brow[pass] + k0 + sq;
        const int so = srow * SMH_STRIDE + sq;
        cp16(As + so, ap, rok);
        cp16(As + so + 8, ap + 8, rok);
        cp16(Bs + so, bp, true);
        cp16(Bs + so + 8, bp + 8, true);
    };

    auto compute = [&](int buf) {
        const uint32_t aS = smb + (uint32_t)(buf * SMH_BUF * 2);
        const uint32_t bS = aS + SMH_MAT * 2;
#pragma unroll
        for (int ks = 0; ks < 2; ++ks) {
            const uint32_t kbb = ks * 32;
            uint32_t bfr[4][2];
#pragma unroll
            for (int ntp = 0; ntp < 2; ++ntp) {
                uint32_t r0, r1, r2, r3;
                LDSM_X4(r0, r1, r2, r3,
                        bS + boff + (uint32_t)(ntp * 16 * SMH_STRIDE * 2) + kbb);
                bfr[2 * ntp][0] = r0; bfr[2 * ntp][1] = r1;
                bfr[2 * ntp + 1][0] = r2; bfr[2 * ntp + 1][1] = r3;
            }
#pragma unroll
            for (int mt = 0; mt < 4; ++mt) {
                uint32_t a0, a1, a2, a3;
                LDSM_X4(a0, a1, a2, a3,
                        aS + aoff + (uint32_t)(mt * 16 * SMH_STRIDE * 2) + kbb);
#pragma unroll
                for (int nt = 0; nt < 4; ++nt)
                    MMA_F16(acc[mt][nt], a0, a1, a2, a3, bfr[nt][0], bfr[nt][1]);
            }
        }
    };

    stage(0, 0);
    asm volatile("cp.async.commit_group;" ::: "memory");
    stage(1, 1);
    asm volatile("cp.async.commit_group;" ::: "memory");

#pragma unroll 1
    for (int cc = 0; cc < T; ++cc) {
        asm volatile("cp.async.wait_group %0;" :: "n"(1) : "memory");
        __syncthreads();
        if (cc + 2 < T) stage(cc + 2, (cc + 2) % N_STAGE);
        asm volatile("cp.async.commit_group;" ::: "memory");
        compute(cc % N_STAGE);
    }

#pragma unroll
    for (int mt = 0; mt < 4; ++mt) {
#pragma unroll
        for (int rr = 0; rr < 2; ++rr) {
            const int r = bm + wm * 64 + mt * 16 + g + rr * 8;
            if (r < p.M) {
                const int cb = bn + wn * 32;
#pragma unroll
                for (int nt = 0; nt < 4; ++nt) {
                    const int c = nt * 8 + t4 * 2;
                    float ox = acc[mt][nt][rr * 2 + 0];
                    float oy = acc[mt][nt][rr * 2 + 1];
                    if (p.add) {
                        __half2 av = *(const __half2*)(p.add + (size_t)r * p.N + cb + c);
                        float2 af = __half22float2(av);
                        ox += af.x; oy += af.y;
                    }
                    if (p.bias) {
                        ox = fmaxf(ox + p.bias[cb + c], 0.f);
                        oy = fmaxf(oy + p.bias[cb + c + 1], 0.f);
                    }
                    if (p.out_half) {
                        *(__half2*)((__half*)p.out + (size_t)r * p.N + cb + c) =
                            __floats2half2_rn(ox, oy);
                    } else {
                        *(float2*)((float*)p.out + (size_t)r * p.N + cb + c) =
                            make_float2(ox, oy);
                    }
                }
            }
        }
    }
}

// ---------------- launch (single stream, 10 launches) ------------------------
extern "C" void kernel_launch(void* const* d_in, const int* in_sizes, int n_in,
                              void* d_out, int out_size) {
    const float* x_user = (const float*)d_in[0];
    const float* x_biz  = (const float*)d_in[1];
    const int* e_src = (const int*)d_in[2];
    const int* e_dst = (const int*)d_in[3];
    const float* b1_ub   = (const float*)d_in[6];
    const float* b1_bu   = (const float*)d_in[9];
    const float* b2_ub   = (const float*)d_in[12];
    const float* b2_bu   = (const float*)d_in[15];

    float* o_user = (float*)d_out;
    float* o_biz  = (float*)d_out + (size_t)N_USER * D_OUT;

    __half *xh_u, *xh_b, *mean_b1, *mean_u1, *h_biz, *h_user, *mean_b2, *y, *mean_y, *wt;
    float *inv_b, *inv_u;
    int *cnt_u, *cnt_b, *off_u, *off_b, *cur_u, *cur_b, *adj_u, *adj_b, *bsum;
    cudaGetSymbolAddress((void**)&xh_u,    g_xh_user);
    cudaGetSymbolAddress((void**)&xh_b,    g_xh_biz);
    cudaGetSymbolAddress((void**)&mean_b1, g_mean_b1);
    cudaGetSymbolAddress((void**)&mean_u1, g_mean_u1);
    cudaGetSymbolAddress((void**)&h_biz,   g_h_biz);
    cudaGetSymbolAddress((void**)&h_user,  g_h_user);
    cudaGetSymbolAddress((void**)&mean_b2, g_mean_b2);
    cudaGetSymbolAddress((void**)&y,       g_y);
    cudaGetSymbolAddress((void**)&mean_y,  g_mean_y);
    cudaGetSymbolAddress((void**)&wt,      g_wt);
    cudaGetSymbolAddress((void**)&inv_b,   g_inv_biz);
    cudaGetSymbolAddress((void**)&inv_u,   g_inv_user);
    cudaGetSymbolAddress((void**)&cnt_u,   g_cnt_user);
    cudaGetSymbolAddress((void**)&cnt_b,   g_cnt_biz);
    cudaGetSymbolAddress((void**)&off_u,   g_off_user);
    cudaGetSymbolAddress((void**)&off_b,   g_off_biz);
    cudaGetSymbolAddress((void**)&cur_u,   g_cur_user);
    cudaGetSymbolAddress((void**)&cur_b,   g_cur_biz);
    cudaGetSymbolAddress((void**)&adj_u,   g_adj_user);
    cudaGetSymbolAddress((void**)&adj_b,   g_adj_biz);
    cudaGetSymbolAddress((void**)&bsum,    g_bsum);

    cudaGetLastError();
    cudaFuncSetAttribute(sage_mma_batched,
                         cudaFuncAttributeMaxDynamicSharedMemorySize, SMEM_BYTES);

    // (1) prep (fp16 round + zero counters) + 8 weight transposes, one launch
    {
        const int prepBlocks = (N_USER * D_IN / 4 + N_BIZ * D_IN / 4 + 255) / 256;
        TransProbs tp;
        tp.W[0] = (const float*)d_in[4];  tp.W[1] = (const float*)d_in[5];
        tp.W[2] = (const float*)d_in[7];  tp.W[3] = (const float*)d_in[8];
        tp.W[4] = (const float*)d_in[10]; tp.W[5] = (const float*)d_in[11];
        tp.W[6] = (const float*)d_in[13]; tp.W[7] = (const float*)d_in[14];
        prep_trans_kernel<<<prepBlocks + 1024, 256>>>(
            (const float4*)x_user, (const float4*)x_biz,
            (__half2*)xh_u, (__half2*)xh_b, cnt_u, cnt_b, tp, wt, prepBlocks);
    }
    // (2-4) CSR build
    hist_kernel<<<(NEDGE + 255) / 256, 256>>>(e_src, e_dst, cnt_u, cnt_b, NEDGE);
    scanA_kernel<<<NBLK_TOT, 1024>>>(cnt_u, cnt_b, bsum);
    scanC_kernel<<<NBLK_TOT, 1024>>>(cnt_u, cnt_b, bsum, off_u, cur_u, inv_u,
                                     off_b, cur_b, inv_b);
    // (5) fill
    fill_kernel<<<(NEDGE + 255) / 256, 256>>>(e_src, e_dst, cur_u, cur_b,
                                              adj_u, adj_b, NEDGE);

    // (6) L1 gathers fused: mean_b1 + mean_u1
    {
        GatherProb p0{(const uint4*)xh_u, off_b, adj_b, inv_b, (uint4*)mean_b1,
                      D_IN / 8, N_BIZ, (N_BIZ + 1) / 2};
        GatherProb p1{(const uint4*)xh_b, off_u, adj_u, inv_u, (uint4*)mean_u1,
                      D_IN / 8, N_USER, (N_USER + 1) / 2};
        gather2_kernel<<<p0.nblk + p1.nblk, 64>>>(p0, p1);
    }

    // (7) L1 GEMMs batched: h_biz + h_user
    {
        GProb q0{mean_b1, xh_b, wt + 0 * 131072, wt + 1 * 131072, b1_ub, nullptr,
                 h_biz, N_BIZ, D_IN, D_H, 2, 1, (N_BIZ + 127) / 128};
        GProb q1{mean_u1, xh_u, wt + 2 * 131072, wt + 3 * 131072, b1_bu, nullptr,
                 h_user, N_USER, D_IN, D_H, 2, 1, (N_USER + 127) / 128};
        dim3 grd(D_H / 128, (N_USER + 127) / 128, 2);
        sage_mma_batched<<<grd, 256, SMEM_BYTES>>>(q0, q1);
    }

    // (8) y = h_biz @ W2_l_bu (fp16, M=50k)
    {
        GProb q0{h_biz, h_biz, wt + 6 * 131072, wt + 6 * 131072, nullptr, nullptr,
                 y, N_BIZ, D_H, D_OUT, 1, 1, (N_BIZ + 127) / 128};
        dim3 grd(D_OUT / 128, (N_BIZ + 127) / 128, 1);
        sage_mma_batched<<<grd, 256, SMEM_BYTES>>>(q0, q0);
    }

    // (9) L2 gathers fused: mean_b2 (from h_user, d8=64) + mean_y (from y, d8=32)
    {
        GatherProb p0{(const uint4*)h_user, off_b, adj_b, inv_b, (uint4*)mean_b2,
                      D_H / 8, N_BIZ, N_BIZ};
        GatherProb p1{(const uint4*)y, off_u, adj_u, inv_u, (uint4*)mean_y,
                      D_OUT / 8, N_USER, (N_USER + 1) / 2};
        gather2_kernel<<<p0.nblk + p1.nblk, 64>>>(p0, p1);
    }

    // (10) final GEMMs batched: o_biz + o_user
    {
        GProb q0{mean_b2, h_biz, wt + 4 * 131072, wt + 5 * 131072, b2_ub, nullptr,
                 o_biz, N_BIZ, D_H, D_OUT, 2, 0, (N_BIZ + 127) / 128};
        GProb q1{h_user, h_user, wt + 7 * 131072, wt + 7 * 131072, b2_bu, mean_y,
                 o_user, N_USER, D_H, D_OUT, 1, 0, (N_USER + 127) / 128};
        dim3 grd(D_OUT / 128, (N_USER + 127) / 128, 2);
        sage_mma_batched<<<grd, 256, SMEM_BYTES>>>(q0, q1);
    }
}

// round 16
// speedup vs baseline: 1.1147x; 1.0388x over previous
#include <cuda_runtime.h>
#include <cuda_fp16.h>
#include <cstdint>

#define N_USER 100000
#define N_BIZ  50000
#define NEDGE  500000
#define D_IN   256
#define D_H    512
#define D_OUT  256

#define NBLK_U 98
#define NBLK_B 49
#define NBLK_TOT (NBLK_U + NBLK_B)

// ---------------- scratch (static device globals) ----------------------------
__device__ __half g_xh_user[(size_t)N_USER * D_IN];
__device__ __half g_xh_biz[(size_t)N_BIZ * D_IN];
__device__ __half g_mean_b1[(size_t)N_BIZ * D_IN];
__device__ __half g_mean_u1[(size_t)N_USER * D_IN];
__device__ __half g_h_biz[(size_t)N_BIZ * D_H];
__device__ __half g_h_user[(size_t)N_USER * D_H];
__device__ __half g_mean_b2[(size_t)N_BIZ * D_H];
__device__ __half g_y[(size_t)N_BIZ * D_OUT];
__device__ __half g_mean_y[(size_t)N_USER * D_OUT];
__device__ __half g_wt[8 * 131072];
__device__ float g_inv_biz[N_BIZ];
__device__ float g_inv_user[N_USER];
__device__ int g_cnt_user[N_USER];
__device__ int g_cnt_biz[N_BIZ];
__device__ int g_off_user[N_USER + 1];
__device__ int g_off_biz[N_BIZ + 1];
__device__ int g_cur_user[N_USER];
__device__ int g_cur_biz[N_BIZ];
__device__ int g_adj_user[NEDGE];
__device__ int g_adj_biz[NEDGE];
__device__ int g_bsum[NBLK_TOT];

// ---------------- helpers ----------------------------------------------------
static __device__ __forceinline__ void cp16(void* sdst, const void* gsrc, bool pred) {
    uint32_t s;
    asm("{ .reg .u64 t; cvta.to.shared.u64 t, %1; cvt.u32.u64 %0, t; }"
        : "=r"(s) : "l"(sdst));
    const int sz = pred ? 16 : 0;
    asm volatile("cp.async.cg.shared.global [%0], [%1], 16, %2;"
                 :: "r"(s), "l"(gsrc), "r"(sz) : "memory");
}
#define LDSM_X4(r0, r1, r2, r3, addr)                                           \
    asm volatile("ldmatrix.sync.aligned.m8n8.x4.shared.b16 {%0,%1,%2,%3}, [%4];" \
                 : "=r"(r0), "=r"(r1), "=r"(r2), "=r"(r3) : "r"(addr))
#define MMA_F16(d, a0, a1, a2, a3, b0, b1)                                      \
    asm volatile("mma.sync.aligned.m16n8k16.row.col.f32.f16.f16.f32 "           \
                 "{%0,%1,%2,%3}, {%4,%5,%6,%7}, {%8,%9}, {%0,%1,%2,%3};"        \
                 : "+f"((d)[0]), "+f"((d)[1]), "+f"((d)[2]), "+f"((d)[3])       \
                 : "r"(a0), "r"(a1), "r"(a2), "r"(a3), "r"(b0), "r"(b1))

// ---------------- fused prep + transpose (one launch) ------------------------
struct TransProbs { const float* W[8]; };

__global__ void prep_trans_kernel(const float4* __restrict__ xu,
                                  const float4* __restrict__ xb,
                                  __half2* __restrict__ xhu, __half2* __restrict__ xhb,
                                  int* __restrict__ cnt_u, int* __restrict__ cnt_b,
                                  TransProbs tp, __half* __restrict__ wt,
                                  int prepBlocks) {
    __shared__ float tbuf[32][33];
    if ((int)blockIdx.x < prepBlocks) {
        const int n4u = N_USER * D_IN / 4, n4b = N_BIZ * D_IN / 4;
        int i = blockIdx.x * 256 + threadIdx.x;
        if (i < n4u) {
            float4 v = __ldg(xu + i);
            xhu[i * 2] = __floats2half2_rn(v.x, v.y);
            xhu[i * 2 + 1] = __floats2half2_rn(v.z, v.w);
        } else if (i < n4u + n4b) {
            int j = i - n4u;
            float4 v = __ldg(xb + j);
            xhb[j * 2] = __floats2half2_rn(v.x, v.y);
            xhb[j * 2 + 1] = __floats2half2_rn(v.z, v.w);
        }
        if (i < N_USER) cnt_u[i] = 0;
        if (i < N_BIZ) cnt_b[i] = 0;
    } else {
        const int t = blockIdx.x - prepBlocks;   // 0..1023 (128 tiles x 8 mats)
        const int m = t >> 7;
        const int rem = t & 127;
        const int K = (m < 4) ? D_IN : D_H;
        const int N = (m < 4) ? D_H : D_OUT;
        const int ntiles = N / 32;
        const int n0 = (rem % ntiles) * 32;
        const int k0 = (rem / ntiles) * 32;
        const float* __restrict__ W = tp.W[m];
        __half* __restrict__ Wt = wt + (size_t)m * 131072;
        const int tx = threadIdx.x & 31, ty = threadIdx.x >> 5;   // ty 0..7
#pragma unroll
        for (int i = 0; i < 4; i++)
            tbuf[ty + i * 8][tx] = W[(size_t)(k0 + ty + i * 8) * N + n0 + tx];
        __syncthreads();
#pragma unroll
        for (int i = 0; i < 4; i++)
            Wt[(size_t)(n0 + ty + i * 8) * K + k0 + tx] =
                __float2half_rn(tbuf[tx][ty + i * 8]);
    }
}

// ---------------- CSR build --------------------------------------------------
__global__ void hist_kernel(const int* __restrict__ e_src,
                            const int* __restrict__ e_dst,
                            int* __restrict__ cnt_u, int* __restrict__ cnt_b, int E) {
    int i = blockIdx.x * blockDim.x + threadIdx.x;
    if (i < E) {
        atomicAdd(&cnt_u[e_src[i]], 1);
        atomicAdd(&cnt_b[e_dst[i]], 1);
    }
}

__global__ void scanA_kernel(const int* __restrict__ cnt_u,
                             const int* __restrict__ cnt_b,
                             int* __restrict__ bsum) {
    __shared__ int ws[32];
    const int b = blockIdx.x, tid = threadIdx.x;
    const int lane = tid & 31, wid = tid >> 5;
    const int* cnt = (b < NBLK_U) ? cnt_u : cnt_b;
    const int n = (b < NBLK_U) ? N_USER : N_BIZ;
    const int base = ((b < NBLK_U) ? b : b - NBLK_U) * 1024;
    const int i = base + tid;
    int v = (i < n) ? cnt[i] : 0;
#pragma unroll
    for (int s = 16; s > 0; s >>= 1) v += __shfl_down_sync(0xFFFFFFFFu, v, s);
    if (lane == 0) ws[wid] = v;
    __syncthreads();
    if (wid == 0) {
        int w = ws[lane];
#pragma unroll
        for (int s = 16; s > 0; s >>= 1) w += __shfl_down_sync(0xFFFFFFFFu, w, s);
        if (lane == 0) bsum[b] = w;
    }
}

// scanC with inlined carry computation (replaces scanB)
__global__ void scanC_kernel(const int* __restrict__ cnt_u,
                             const int* __restrict__ cnt_b,
                             const int* __restrict__ bsum,
                             int* __restrict__ off_u, int* __restrict__ cur_u,
                             float* __restrict__ inv_u,
                             int* __restrict__ off_b, int* __restrict__ cur_b,
                             float* __restrict__ inv_b) {
    __shared__ int ws[32];
    __shared__ int carry_s;
    const int b = blockIdx.x, tid = threadIdx.x;
    const int lane = tid & 31, wid = tid >> 5;
    const bool isU = (b < NBLK_U);

    {
        int contrib = 0;
        if (tid < NBLK_TOT) {
            const bool in = isU ? (tid < b) : (tid >= NBLK_U && tid < b);
            if (in) contrib = bsum[tid];
        }
        int v = contrib;
#pragma unroll
        for (int s = 16; s > 0; s >>= 1) v += __shfl_down_sync(0xFFFFFFFFu, v, s);
        if (lane == 0) ws[wid] = v;
        __syncthreads();
        if (wid == 0) {
            int w = ws[lane];
#pragma unroll
            for (int s = 16; s > 0; s >>= 1) w += __shfl_down_sync(0xFFFFFFFFu, w, s);
            if (lane == 0) carry_s = w;
        }
        __syncthreads();
    }
    const int carry = carry_s;
    __syncthreads();

    const int* cnt = isU ? cnt_u : cnt_b;
    int* off = isU ? off_u : off_b;
    int* cur = isU ? cur_u : cur_b;
    float* inv = isU ? inv_u : inv_b;
    const int n = isU ? N_USER : N_BIZ;
    const int base = (isU ? b : b - NBLK_U) * 1024;
    const int i = base + tid;
    const int v = (i < n) ? cnt[i] : 0;
    int x = v;
#pragma unroll
    for (int s = 1; s < 32; s <<= 1) {
        int y = __shfl_up_sync(0xFFFFFFFFu, x, s);
        if (lane >= s) x += y;
    }
    if (lane == 31) ws[wid] = x;
    __syncthreads();
    if (wid == 0) {
        int w = ws[lane];
#pragma unroll
        for (int s = 1; s < 32; s <<= 1) {
            int y = __shfl_up_sync(0xFFFFFFFFu, w, s);
            if (lane >= s) w += y;
        }
        ws[lane] = w;
    }
    __syncthreads();
    const int woff = (wid == 0) ? 0 : ws[wid - 1];
    const int excl = carry + woff + x - v;
    if (i < n) {
        off[i] = excl; cur[i] = excl;
        inv[i] = 1.0f / fmaxf((float)v, 1.0f);
        if (i == n - 1) off[n] = excl + v;
    }
}

__global__ void fill_kernel(const int* __restrict__ e_src,
                            const int* __restrict__ e_dst,
                            int* __restrict__ cur_u, int* __restrict__ cur_b,
                            int* __restrict__ adj_u, int* __restrict__ adj_b, int E) {
    int i = blockIdx.x * blockDim.x + threadIdx.x;
    if (i < E) {
        const int s = e_src[i], d = e_dst[i];
        adj_b[atomicAdd(&cur_b[d], 1)] = s;
        adj_u[atomicAdd(&cur_u[s], 1)] = d;
    }
}

// ------- dual gather-mean (64-thread blocks, zero smem, MLP=2 — R13) ---------
struct GatherProb {
    const uint4* feat; const int* off; const int* adj; const float* inv;
    uint4* out; int d8; int nrows; int nblk;
};

__global__ void gather2_kernel(GatherProb p0, GatherProb p1) {
    const bool first = (blockIdx.x < (unsigned)p0.nblk);
    const GatherProb p = first ? p0 : p1;
    const int lb = first ? blockIdx.x : blockIdx.x - p0.nblk;
    const int d8 = p.d8;
    const int rpb = 64 / d8;
    const int n = lb * rpb + (int)(threadIdx.x / d8);
    if (n >= p.nrows) return;
    const int tid = threadIdx.x & (d8 - 1);

    const int s = __ldg(p.off + n), e = __ldg(p.off + n + 1);
    float2 a0[4], a1[4];
#pragma unroll
    for (int j = 0; j < 4; j++) { a0[j] = make_float2(0.f, 0.f); a1[j] = make_float2(0.f, 0.f); }
    int i = s;
    for (; i + 1 < e; i += 2) {
        const int s0 = __ldg(p.adj + i), s1 = __ldg(p.adj + i + 1);
        const uint4 v0 = __ldg(p.feat + (size_t)s0 * d8 + tid);
        const uint4 v1 = __ldg(p.feat + (size_t)s1 * d8 + tid);
        const __half2* h0 = (const __half2*)&v0;
        const __half2* h1 = (const __half2*)&v1;
#pragma unroll
        for (int j = 0; j < 4; j++) {
            float2 f0 = __half22float2(h0[j]);
            float2 f1 = __half22float2(h1[j]);
            a0[j].x += f0.x; a0[j].y += f0.y;
            a1[j].x += f1.x; a1[j].y += f1.y;
        }
    }
    if (i < e) {
        const int s0 = __ldg(p.adj + i);
        const uint4 v0 = __ldg(p.feat + (size_t)s0 * d8 + tid);
        const __half2* h0 = (const __half2*)&v0;
#pragma unroll
        for (int j = 0; j < 4; j++) {
            float2 f0 = __half22float2(h0[j]);
            a0[j].x += f0.x; a0[j].y += f0.y;
        }
    }
    const float sc = __ldg(p.inv + n);
    uint4 o;
    __half2* oh = (__half2*)&o;
#pragma unroll
    for (int j = 0; j < 4; j++)
        oh[j] = __floats2half2_rn((a0[j].x + a1[j].x) * sc, (a0[j].y + a1[j].y) * sc);
    p.out[(size_t)n * d8 + tid] = o;
}

// ---------------- fp16 mma.sync SAGE GEMM (batched 2-problem, R13) -----------
#define SMH_STRIDE 40
#define SMH_MAT    (128 * SMH_STRIDE)
#define SMH_BUF    (2 * SMH_MAT)
#define N_STAGE    3
#define SMEM_BYTES (N_STAGE * SMH_BUF * 2)   // 61440 B

struct GProb {
    const __half* A; const __half* X; const __half* Wtl; const __half* Wtr;
    const float* bias; const __half* add; void* out;
    int M, K, N, npass, out_half, ytiles;
};

__global__ void __launch_bounds__(256, 2)
sage_mma_batched(GProb q0, GProb q1) {
    const GProb p = (blockIdx.z == 0) ? q0 : q1;
    if ((int)blockIdx.y >= p.ytiles) return;

    extern __shared__ __half sm[];
    uint32_t smb;
    asm("{ .reg .u64 t; cvta.to.shared.u64 t, %1; cvt.u32.u64 %0, t; }"
        : "=r"(smb) : "l"(sm));
    const int tid = threadIdx.x, lane = tid & 31, wid = tid >> 5;
    const int wm = wid >> 2, wn = wid & 3;
    const int g = lane >> 2, t4 = lane & 3;

    const int bm = blockIdx.y * 128, bn = blockIdx.x * 128;
    const int srow = tid >> 1;
    const int sq = (tid & 1) * 16;
    const int grow = bm + srow;
    const bool rok = grow < p.M;

    const __half* arow[2];
    arow[0] = p.A + (size_t)(rok ? grow : 0) * p.K;
    arow[1] = p.X + (size_t)(rok ? grow : 0) * p.K;
    const __half* brow[2];
    brow[0] = p.Wtl + (size_t)(bn + srow) * p.K;
    brow[1] = p.Wtr + (size_t)(bn + srow) * p.K;

    const int CH = p.K >> 5;
    const int T = p.npass * CH;

    const int lr = lane & 7, lmi = lane >> 3;
    const uint32_t aoff = (uint32_t)(((wm * 64 + (lmi & 1) * 8 + lr) * SMH_STRIDE
                                      + (lmi >> 1) * 8) * 2);
    const uint32_t boff = (uint32_t)(((wn * 32 + (lmi >> 1) * 8 + lr) * SMH_STRIDE
                                      + (lmi & 1) * 8) * 2);

    float acc[4][4][4];
#pragma unroll
    for (int i = 0; i < 4; i++)
#pragma unroll
        for (int j = 0; j < 4; j++)
#pragma unroll
            for (int r = 0; r < 4; r++) acc[i][j][r] = 0.0f;

    auto stage = [&](int cc, int buf) {
        const int pass = (cc >= CH) ? 1 : 0;
        const int k0 = (cc - pass * CH) << 5;
        __half* As = sm + buf * SMH_BUF;
        __half* Bs = As + SMH_MAT;
        const __half* ap = arow[pass] + k0 + sq;
        const __half* bp = brow[pass] + k0 + sq;
        const int so = srow * SMH_STRIDE + sq;
        cp16(As + so, ap, rok);
        cp16(As + so + 8, ap + 8, rok);
        cp16(Bs + so, bp, true);
        cp16(Bs + so + 8, bp + 8, true);
    };

    auto compute = [&](int buf) {
        const uint32_t aS = smb + (uint32_t)(buf * SMH_BUF * 2);
        const uint32_t bS = aS + SMH_MAT * 2;
#pragma unroll
        for (int ks = 0; ks < 2; ++ks) {
            const uint32_t kbb = ks * 32;
            uint32_t bfr[4][2];
#pragma unroll
            for (int ntp = 0; ntp < 2; ++ntp) {
                uint32_t r0, r1, r2, r3;
                LDSM_X4(r0, r1, r2, r3,
                        bS + boff + (uint32_t)(ntp * 16 * SMH_STRIDE * 2) + kbb);
                bfr[2 * ntp][0] = r0; bfr[2 * ntp][1] = r1;
                bfr[2 * ntp + 1][0] = r2; bfr[2 * ntp + 1][1] = r3;
            }
#pragma unroll
            for (int mt = 0; mt < 4; ++mt) {
                uint32_t a0, a1, a2, a3;
                LDSM_X4(a0, a1, a2, a3,
                        aS + aoff + (uint32_t)(mt * 16 * SMH_STRIDE * 2) + kbb);
#pragma unroll
                for (int nt = 0; nt < 4; ++nt)
                    MMA_F16(acc[mt][nt], a0, a1, a2, a3, bfr[nt][0], bfr[nt][1]);
            }
        }
    };

    stage(0, 0);
    asm volatile("cp.async.commit_group;" ::: "memory");
    stage(1, 1);
    asm volatile("cp.async.commit_group;" ::: "memory");

#pragma unroll 1
    for (int cc = 0; cc < T; ++cc) {
        asm volatile("cp.async.wait_group %0;" :: "n"(1) : "memory");
        __syncthreads();
        if (cc + 2 < T) stage(cc + 2, (cc + 2) % N_STAGE);
        asm volatile("cp.async.commit_group;" ::: "memory");
        compute(cc % N_STAGE);
    }

#pragma unroll
    for (int mt = 0; mt < 4; ++mt) {
#pragma unroll
        for (int rr = 0; rr < 2; ++rr) {
            const int r = bm + wm * 64 + mt * 16 + g + rr * 8;
            if (r < p.M) {
                const int cb = bn + wn * 32;
#pragma unroll
                for (int nt = 0; nt < 4; ++nt) {
                    const int c = nt * 8 + t4 * 2;
                    float ox = acc[mt][nt][rr * 2 + 0];
                    float oy = acc[mt][nt][rr * 2 + 1];
                    if (p.add) {
                        __half2 av = *(const __half2*)(p.add + (size_t)r * p.N + cb + c);
                        float2 af = __half22float2(av);
                        ox += af.x; oy += af.y;
                    }
                    if (p.bias) {
                        ox = fmaxf(ox + p.bias[cb + c], 0.f);
                        oy = fmaxf(oy + p.bias[cb + c + 1], 0.f);
                    }
                    if (p.out_half) {
                        *(__half2*)((__half*)p.out + (size_t)r * p.N + cb + c) =
                            __floats2half2_rn(ox, oy);
                    } else {
                        *(float2*)((float*)p.out + (size_t)r * p.N + cb + c) =
                            make_float2(ox, oy);
                    }
                }
            }
        }
    }
}

// ---------------- launch (single stream, 10 launches) ------------------------
extern "C" void kernel_launch(void* const* d_in, const int* in_sizes, int n_in,
                              void* d_out, int out_size) {
    const float* x_user = (const float*)d_in[0];
    const float* x_biz  = (const float*)d_in[1];
    const int* e_src = (const int*)d_in[2];
    const int* e_dst = (const int*)d_in[3];
    const float* b1_ub   = (const float*)d_in[6];
    const float* b1_bu   = (const float*)d_in[9];
    const float* b2_ub   = (const float*)d_in[12];
    const float* b2_bu   = (const float*)d_in[15];

    float* o_user = (float*)d_out;
    float* o_biz  = (float*)d_out + (size_t)N_USER * D_OUT;

    __half *xh_u, *xh_b, *mean_b1, *mean_u1, *h_biz, *h_user, *mean_b2, *y, *mean_y, *wt;
    float *inv_b, *inv_u;
    int *cnt_u, *cnt_b, *off_u, *off_b, *cur_u, *cur_b, *adj_u, *adj_b, *bsum;
    cudaGetSymbolAddress((void**)&xh_u,    g_xh_user);
    cudaGetSymbolAddress((void**)&xh_b,    g_xh_biz);
    cudaGetSymbolAddress((void**)&mean_b1, g_mean_b1);
    cudaGetSymbolAddress((void**)&mean_u1, g_mean_u1);
    cudaGetSymbolAddress((void**)&h_biz,   g_h_biz);
    cudaGetSymbolAddress((void**)&h_user,  g_h_user);
    cudaGetSymbolAddress((void**)&mean_b2, g_mean_b2);
    cudaGetSymbolAddress((void**)&y,       g_y);
    cudaGetSymbolAddress((void**)&mean_y,  g_mean_y);
    cudaGetSymbolAddress((void**)&wt,      g_wt);
    cudaGetSymbolAddress((void**)&inv_b,   g_inv_biz);
    cudaGetSymbolAddress((void**)&inv_u,   g_inv_user);
    cudaGetSymbolAddress((void**)&cnt_u,   g_cnt_user);
    cudaGetSymbolAddress((void**)&cnt_b,   g_cnt_biz);
    cudaGetSymbolAddress((void**)&off_u,   g_off_user);
    cudaGetSymbolAddress((void**)&off_b,   g_off_biz);
    cudaGetSymbolAddress((void**)&cur_u,   g_cur_user);
    cudaGetSymbolAddress((void**)&cur_b,   g_cur_biz);
    cudaGetSymbolAddress((void**)&adj_u,   g_adj_user);
    cudaGetSymbolAddress((void**)&adj_b,   g_adj_biz);
    cudaGetSymbolAddress((void**)&bsum,    g_bsum);

    cudaGetLastError();
    cudaFuncSetAttribute(sage_mma_batched,
                         cudaFuncAttributeMaxDynamicSharedMemorySize, SMEM_BYTES);

    // (1) prep (fp16 round + zero counters) + 8 weight transposes, one launch
    {
        const int prepBlocks = (N_USER * D_IN / 4 + N_BIZ * D_IN / 4 + 255) / 256;
        TransProbs tp;
        tp.W[0] = (const float*)d_in[4];  tp.W[1] = (const float*)d_in[5];
        tp.W[2] = (const float*)d_in[7];  tp.W[3] = (const float*)d_in[8];
        tp.W[4] = (const float*)d_in[10]; tp.W[5] = (const float*)d_in[11];
        tp.W[6] = (const float*)d_in[13]; tp.W[7] = (const float*)d_in[14];
        prep_trans_kernel<<<prepBlocks + 1024, 256>>>(
            (const float4*)x_user, (const float4*)x_biz,
            (__half2*)xh_u, (__half2*)xh_b, cnt_u, cnt_b, tp, wt, prepBlocks);
    }
    // (2-4) CSR build (scanB folded into scanC)
    hist_kernel<<<(NEDGE + 255) / 256, 256>>>(e_src, e_dst, cnt_u, cnt_b, NEDGE);
    scanA_kernel<<<NBLK_TOT, 1024>>>(cnt_u, cnt_b, bsum);
    scanC_kernel<<<NBLK_TOT, 1024>>>(cnt_u, cnt_b, bsum, off_u, cur_u, inv_u,
                                     off_b, cur_b, inv_b);
    // (5) fill
    fill_kernel<<<(NEDGE + 255) / 256, 256>>>(e_src, e_dst, cur_u, cur_b,
                                              adj_u, adj_b, NEDGE);

    // (6) L1 gathers fused: mean_b1 + mean_u1
    {
        GatherProb p0{(const uint4*)xh_u, off_b, adj_b, inv_b, (uint4*)mean_b1,
                      D_IN / 8, N_BIZ, (N_BIZ + 1) / 2};
        GatherProb p1{(const uint4*)xh_b, off_u, adj_u, inv_u, (uint4*)mean_u1,
                      D_IN / 8, N_USER, (N_USER + 1) / 2};
        gather2_kernel<<<p0.nblk + p1.nblk, 64>>>(p0, p1);
    }

    // (7) L1 GEMMs batched: h_biz + h_user
    {
        GProb q0{mean_b1, xh_b, wt + 0 * 131072, wt + 1 * 131072, b1_ub, nullptr,
                 h_biz, N_BIZ, D_IN, D_H, 2, 1, (N_BIZ + 127) / 128};
        GProb q1{mean_u1, xh_u, wt + 2 * 131072, wt + 3 * 131072, b1_bu, nullptr,
                 h_user, N_USER, D_IN, D_H, 2, 1, (N_USER + 127) / 128};
        dim3 grd(D_H / 128, (N_USER + 127) / 128, 2);
        sage_mma_batched<<<grd, 256, SMEM_BYTES>>>(q0, q1);
    }

    // (8) y = h_biz @ W2_l_bu (fp16, M=50k)
    {
        GProb q0{h_biz, h_biz, wt + 6 * 131072, wt + 6 * 131072, nullptr, nullptr,
                 y, N_BIZ, D_H, D_OUT, 1, 1, (N_BIZ + 127) / 128};
        dim3 grd(D_OUT / 128, (N_BIZ + 127) / 128, 1);
        sage_mma_batched<<<grd, 256, SMEM_BYTES>>>(q0, q0);
    }

    // (9) L2 gathers fused: mean_b2 (from h_user, d8=64) + mean_y (from y, d8=32)
    {
        GatherProb p0{(const uint4*)h_user, off_b, adj_b, inv_b, (uint4*)mean_b2,
                      D_H / 8, N_BIZ, N_BIZ};
        GatherProb p1{(const uint4*)y, off_u, adj_u, inv_u, (uint4*)mean_y,
                      D_OUT / 8, N_USER, (N_USER + 1) / 2};
        gather2_kernel<<<p0.nblk + p1.nblk, 64>>>(p0, p1);
    }

    // (10) final GEMMs batched: o_biz + o_user
    {
        GProb q0{mean_b2, h_biz, wt + 4 * 131072, wt + 5 * 131072, b2_ub, nullptr,
                 o_biz, N_BIZ, D_H, D_OUT, 2, 0, (N_BIZ + 127) / 128};
        GProb q1{h_user, h_user, wt + 7 * 131072, wt + 7 * 131072, b2_bu, mean_y,
                 o_user, N_USER, D_H, D_OUT, 1, 0, (N_USER + 127) / 128};
        dim3 grd(D_OUT / 128, (N_USER + 127) / 128, 2);
        sage_mma_batched<<<grd, 256, SMEM_BYTES>>>(q0, q1);
    }
}

// round 17
// speedup vs baseline: 1.1672x; 1.0471x over previous
#include <cuda_runtime.h>
#include <cuda_fp16.h>
#include <cstdint>

#define N_USER 100000
#define N_BIZ  50000
#define NEDGE  500000
#define D_IN   256
#define D_H    512
#define D_OUT  256

#define NBLK_U 98
#define NBLK_B 49
#define NBLK_TOT (NBLK_U + NBLK_B)

// ---------------- scratch (static device globals) ----------------------------
__device__ __half g_xh_user[(size_t)N_USER * D_IN];
__device__ __half g_xh_biz[(size_t)N_BIZ * D_IN];
__device__ __half g_mean_b1[(size_t)N_BIZ * D_IN];
__device__ __half g_mean_u1[(size_t)N_USER * D_IN];
__device__ __half g_h_biz[(size_t)N_BIZ * D_H];
__device__ __half g_h_user[(size_t)N_USER * D_H];
__device__ __half g_mean_b2[(size_t)N_BIZ * D_H];
__device__ __half g_y[(size_t)N_BIZ * D_OUT];
__device__ __half g_mean_y[(size_t)N_USER * D_OUT];
__device__ __half g_wt[8 * 131072];
__device__ float g_inv_biz[N_BIZ];
__device__ float g_inv_user[N_USER];
__device__ int g_cnt_user[N_USER];
__device__ int g_cnt_biz[N_BIZ];
__device__ int g_off_user[N_USER + 1];
__device__ int g_off_biz[N_BIZ + 1];
__device__ int g_cur_user[N_USER];
__device__ int g_cur_biz[N_BIZ];
__device__ int g_adj_user[NEDGE];
__device__ int g_adj_biz[NEDGE];
__device__ int g_bsum[NBLK_TOT];

// ---------------- helpers ----------------------------------------------------
static __device__ __forceinline__ void cp16(void* sdst, const void* gsrc, bool pred) {
    uint32_t s;
    asm("{ .reg .u64 t; cvta.to.shared.u64 t, %1; cvt.u32.u64 %0, t; }"
        : "=r"(s) : "l"(sdst));
    const int sz = pred ? 16 : 0;
    asm volatile("cp.async.cg.shared.global [%0], [%1], 16, %2;"
                 :: "r"(s), "l"(gsrc), "r"(sz) : "memory");
}
#define LDSM_X4(r0, r1, r2, r3, addr)                                           \
    asm volatile("ldmatrix.sync.aligned.m8n8.x4.shared.b16 {%0,%1,%2,%3}, [%4];" \
                 : "=r"(r0), "=r"(r1), "=r"(r2), "=r"(r3) : "r"(addr))
#define MMA_F16(d, a0, a1, a2, a3, b0, b1)                                      \
    asm volatile("mma.sync.aligned.m16n8k16.row.col.f32.f16.f16.f32 "           \
                 "{%0,%1,%2,%3}, {%4,%5,%6,%7}, {%8,%9}, {%0,%1,%2,%3};"        \
                 : "+f"((d)[0]), "+f"((d)[1]), "+f"((d)[2]), "+f"((d)[3])       \
                 : "r"(a0), "r"(a1), "r"(a2), "r"(a3), "r"(b0), "r"(b1))

// -------- fused prologue: fp16-round features + zero degree counters ---------
__global__ void prep_kernel(const float4* __restrict__ xu, const float4* __restrict__ xb,
                            __half2* __restrict__ xhu, __half2* __restrict__ xhb,
                            int* __restrict__ cnt_u, int* __restrict__ cnt_b) {
    const int n4u = N_USER * D_IN / 4, n4b = N_BIZ * D_IN / 4;
    int i = blockIdx.x * blockDim.x + threadIdx.x;
    if (i < n4u) {
        float4 v = __ldg(xu + i);
        xhu[i * 2] = __floats2half2_rn(v.x, v.y);
        xhu[i * 2 + 1] = __floats2half2_rn(v.z, v.w);
    } else if (i < n4u + n4b) {
        int j = i - n4u;
        float4 v = __ldg(xb + j);
        xhb[j * 2] = __floats2half2_rn(v.x, v.y);
        xhb[j * 2 + 1] = __floats2half2_rn(v.z, v.w);
    }
    if (i < N_USER) cnt_u[i] = 0;
    if (i < N_BIZ) cnt_b[i] = 0;
}

// ---------------- all 8 weight transposes in ONE launch -----------------------
struct TransProbs { const float* W[8]; };

__global__ void transpose_all_kernel(TransProbs tp, __half* __restrict__ wt) {
    const int m = blockIdx.z;
    const int K = (m < 4) ? D_IN : D_H;
    const int N = (m < 4) ? D_H : D_OUT;
    if ((int)blockIdx.x >= N / 32 || (int)blockIdx.y >= K / 32) return;
    const float* __restrict__ W = tp.W[m];
    __half* __restrict__ Wt = wt + (size_t)m * 131072;
    __shared__ float t[32][33];
    int n0 = blockIdx.x * 32, k0 = blockIdx.y * 32;
    int tx = threadIdx.x, ty = threadIdx.y;
#pragma unroll
    for (int i = 0; i < 4; i++)
        t[ty + i * 8][tx] = W[(size_t)(k0 + ty + i * 8) * N + n0 + tx];
    __syncthreads();
#pragma unroll
    for (int i = 0; i < 4; i++)
        Wt[(size_t)(n0 + ty + i * 8) * K + k0 + tx] = __float2half_rn(t[tx][ty + i * 8]);
}

// ---------------- CSR build --------------------------------------------------
__global__ void hist_kernel(const int* __restrict__ e_src,
                            const int* __restrict__ e_dst,
                            int* __restrict__ cnt_u, int* __restrict__ cnt_b, int E) {
    int i = blockIdx.x * blockDim.x + threadIdx.x;
    if (i < E) {
        atomicAdd(&cnt_u[e_src[i]], 1);
        atomicAdd(&cnt_b[e_dst[i]], 1);
    }
}

__global__ void scanA_kernel(const int* __restrict__ cnt_u,
                             const int* __restrict__ cnt_b,
                             int* __restrict__ bsum) {
    __shared__ int ws[32];
    const int b = blockIdx.x, tid = threadIdx.x;
    const int lane = tid & 31, wid = tid >> 5;
    const int* cnt = (b < NBLK_U) ? cnt_u : cnt_b;
    const int n = (b < NBLK_U) ? N_USER : N_BIZ;
    const int base = ((b < NBLK_U) ? b : b - NBLK_U) * 1024;
    const int i = base + tid;
    int v = (i < n) ? cnt[i] : 0;
#pragma unroll
    for (int s = 16; s > 0; s >>= 1) v += __shfl_down_sync(0xFFFFFFFFu, v, s);
    if (lane == 0) ws[wid] = v;
    __syncthreads();
    if (wid == 0) {
        int w = ws[lane];
#pragma unroll
        for (int s = 16; s > 0; s >>= 1) w += __shfl_down_sync(0xFFFFFFFFu, w, s);
        if (lane == 0) bsum[b] = w;
    }
}

__global__ void scanB_kernel(int* __restrict__ bsum) {
    if (threadIdx.x == 0) {
        int run = 0;
        for (int b = 0; b < NBLK_U; ++b) { int t = bsum[b]; bsum[b] = run; run += t; }
        run = 0;
        for (int b = NBLK_U; b < NBLK_TOT; ++b) { int t = bsum[b]; bsum[b] = run; run += t; }
    }
}

__global__ void scanC_kernel(const int* __restrict__ cnt_u,
                             const int* __restrict__ cnt_b,
                             const int* __restrict__ bsum,
                             int* __restrict__ off_u, int* __restrict__ cur_u,
                             float* __restrict__ inv_u,
                             int* __restrict__ off_b, int* __restrict__ cur_b,
                             float* __restrict__ inv_b) {
    __shared__ int ws[32];
    const int b = blockIdx.x, tid = threadIdx.x;
    const int lane = tid & 31, wid = tid >> 5;
    const bool isU = (b < NBLK_U);
    const int* cnt = isU ? cnt_u : cnt_b;
    int* off = isU ? off_u : off_b;
    int* cur = isU ? cur_u : cur_b;
    float* inv = isU ? inv_u : inv_b;
    const int n = isU ? N_USER : N_BIZ;
    const int base = (isU ? b : b - NBLK_U) * 1024;
    const int i = base + tid;
    const int v = (i < n) ? cnt[i] : 0;
    int x = v;
#pragma unroll
    for (int s = 1; s < 32; s <<= 1) {
        int y = __shfl_up_sync(0xFFFFFFFFu, x, s);
        if (lane >= s) x += y;
    }
    if (lane == 31) ws[wid] = x;
    __syncthreads();
    if (wid == 0) {
        int w = ws[lane];
#pragma unroll
        for (int s = 1; s < 32; s <<= 1) {
            int y = __shfl_up_sync(0xFFFFFFFFu, w, s);
            if (lane >= s) w += y;
        }
        ws[lane] = w;
    }
    __syncthreads();
    const int woff = (wid == 0) ? 0 : ws[wid - 1];
    const int excl = bsum[b] + woff + x - v;
    if (i < n) {
        off[i] = excl; cur[i] = excl;
        inv[i] = 1.0f / fmaxf((float)v, 1.0f);
        if (i == n - 1) off[n] = excl + v;
    }
}

__global__ void fill_kernel(const int* __restrict__ e_src,
                            const int* __restrict__ e_dst,
                            int* __restrict__ cur_u, int* __restrict__ cur_b,
                            int* __restrict__ adj_u, int* __restrict__ adj_b, int E) {
    int i = blockIdx.x * blockDim.x + threadIdx.x;
    if (i < E) {
        const int s = e_src[i], d = e_dst[i];
        adj_b[atomicAdd(&cur_b[d], 1)] = s;
        adj_u[atomicAdd(&cur_u[s], 1)] = d;
    }
}

// ------- fused dual gather-mean: two independent problems, one launch --------
// blockDim = 64; rows per block = 64/d8 (d8 = 32 or 64). One warp group per row.
struct GatherProb {
    const uint4* feat; const int* off; const int* adj; const float* inv;
    uint4* out; int d8; int nrows; int nblk;
};

__global__ void gather2_kernel(GatherProb p0, GatherProb p1) {
    const bool first = (blockIdx.x < (unsigned)p0.nblk);
    const GatherProb p = first ? p0 : p1;
    const int lb = first ? blockIdx.x : blockIdx.x - p0.nblk;
    const int d8 = p.d8;
    const int rpb = 64 / d8;
    const int n = lb * rpb + (int)(threadIdx.x / d8);
    if (n >= p.nrows) return;
    const int tid = threadIdx.x & (d8 - 1);

    const int s = __ldg(p.off + n), e = __ldg(p.off + n + 1);
    float2 a0[4], a1[4];
#pragma unroll
    for (int j = 0; j < 4; j++) { a0[j] = make_float2(0.f, 0.f); a1[j] = make_float2(0.f, 0.f); }
    int i = s;
    for (; i + 1 < e; i += 2) {
        const int s0 = __ldg(p.adj + i), s1 = __ldg(p.adj + i + 1);
        const uint4 v0 = __ldg(p.feat + (size_t)s0 * d8 + tid);
        const uint4 v1 = __ldg(p.feat + (size_t)s1 * d8 + tid);
        const __half2* h0 = (const __half2*)&v0;
        const __half2* h1 = (const __half2*)&v1;
#pragma unroll
        for (int j = 0; j < 4; j++) {
            float2 f0 = __half22float2(h0[j]);
            float2 f1 = __half22float2(h1[j]);
            a0[j].x += f0.x; a0[j].y += f0.y;
            a1[j].x += f1.x; a1[j].y += f1.y;
        }
    }
    if (i < e) {
        const int s0 = __ldg(p.adj + i);
        const uint4 v0 = __ldg(p.feat + (size_t)s0 * d8 + tid);
        const __half2* h0 = (const __half2*)&v0;
#pragma unroll
        for (int j = 0; j < 4; j++) {
            float2 f0 = __half22float2(h0[j]);
            a0[j].x += f0.x; a0[j].y += f0.y;
        }
    }
    const float sc = __ldg(p.inv + n);
    uint4 o;
    __half2* oh = (__half2*)&o;
#pragma unroll
    for (int j = 0; j < 4; j++)
        oh[j] = __floats2half2_rn((a0[j].x + a1[j].x) * sc, (a0[j].y + a1[j].y) * sc);
    p.out[(size_t)n * d8 + tid] = o;
}

// ---------------- fp16 mma.sync SAGE GEMM (batched 2-problem) ----------------
#define SMH_STRIDE 40
#define SMH_MAT    (128 * SMH_STRIDE)
#define SMH_BUF    (2 * SMH_MAT)
#define N_STAGE    3
#define SMEM_BYTES (N_STAGE * SMH_BUF * 2)   // 61440 B

struct GProb {
    const __half* A; const __half* X; const __half* Wtl; const __half* Wtr;
    const float* bias; const __half* add; void* out;
    int M, K, N, npass, out_half, ytiles;
};

__global__ void __launch_bounds__(256, 2)
sage_mma_batched(GProb q0, GProb q1) {
    const GProb p = (blockIdx.z == 0) ? q0 : q1;
    if ((int)blockIdx.y >= p.ytiles) return;

    extern __shared__ __half sm[];
    uint32_t smb;
    asm("{ .reg .u64 t; cvta.to.shared.u64 t, %1; cvt.u32.u64 %0, t; }"
        : "=r"(smb) : "l"(sm));
    const int tid = threadIdx.x, lane = tid & 31, wid = tid >> 5;
    const int wm = wid >> 2, wn = wid & 3;
    const int g = lane >> 2, t4 = lane & 3;

    const int bm = blockIdx.y * 128, bn = blockIdx.x * 128;
    const int srow = tid >> 1;
    const int sq = (tid & 1) * 16;
    const int grow = bm + srow;
    const bool rok = grow < p.M;

    const __half* arow[2];
    arow[0] = p.A + (size_t)(rok ? grow : 0) * p.K;
    arow[1] = p.X + (size_t)(rok ? grow : 0) * p.K;
    const __half* brow[2];
    brow[0] = p.Wtl + (size_t)(bn + srow) * p.K;
    brow[1] = p.Wtr + (size_t)(bn + srow) * p.K;

    const int CH = p.K >> 5;
    const int T = p.npass * CH;

    const int lr = lane & 7, lmi = lane >> 3;
    const uint32_t aoff = (uint32_t)(((wm * 64 + (lmi & 1) * 8 + lr) * SMH_STRIDE
                                      + (lmi >> 1) * 8) * 2);
    const uint32_t boff = (uint32_t)(((wn * 32 + (lmi >> 1) * 8 + lr) * SMH_STRIDE
                                      + (lmi & 1) * 8) * 2);

    float acc[4][4][4];
#pragma unroll
    for (int i = 0; i < 4; i++)
#pragma unroll
        for (int j = 0; j < 4; j++)
#pragma unroll
            for (int r = 0; r < 4; r++) acc[i][j][r] = 0.0f;

    auto stage = [&](int cc, int buf) {
        const int pass = (cc >= CH) ? 1 : 0;
        const int k0 = (cc - pass * CH) << 5;
        __half* As = sm + buf * SMH_BUF;
        __half* Bs = As + SMH_MAT;
        const __half* ap = arow[pass] + k0 + sq;
        const __half* bp = brow[pass] + k0 + sq;
        const int so = srow * SMH_STRIDE + sq;
        cp16(As + so, ap, rok);
        cp16(As + so + 8, ap + 8, rok);
        cp16(Bs + so, bp, true);
        cp16(Bs + so + 8, bp + 8, true);
    };

    auto compute = [&](int buf) {
        const uint32_t aS = smb + (uint32_t)(buf * SMH_BUF * 2);
        const uint32_t bS = aS + SMH_MAT * 2;
#pragma unroll
        for (int ks = 0; ks < 2; ++ks) {
            const uint32_t kbb = ks * 32;
            uint32_t bfr[4][2];
#pragma unroll
            for (int ntp = 0; ntp < 2; ++ntp) {
                uint32_t r0, r1, r2, r3;
                LDSM_X4(r0, r1, r2, r3,
                        bS + boff + (uint32_t)(ntp * 16 * SMH_STRIDE * 2) + kbb);
                bfr[2 * ntp][0] = r0; bfr[2 * ntp][1] = r1;
                bfr[2 * ntp + 1][0] = r2; bfr[2 * ntp + 1][1] = r3;
            }
#pragma unroll
            for (int mt = 0; mt < 4; ++mt) {
                uint32_t a0, a1, a2, a3;
                LDSM_X4(a0, a1, a2, a3,
                        aS + aoff + (uint32_t)(mt * 16 * SMH_STRIDE * 2) + kbb);
#pragma unroll
                for (int nt = 0; nt < 4; ++nt)
                    MMA_F16(acc[mt][nt], a0, a1, a2, a3, bfr[nt][0], bfr[nt][1]);
            }
        }
    };

    stage(0, 0);
    asm volatile("cp.async.commit_group;" ::: "memory");
    stage(1, 1);
    asm volatile("cp.async.commit_group;" ::: "memory");

#pragma unroll 1
    for (int cc = 0; cc < T; ++cc) {
        asm volatile("cp.async.wait_group %0;" :: "n"(1) : "memory");
        __syncthreads();
        if (cc + 2 < T) stage(cc + 2, (cc + 2) % N_STAGE);
        asm volatile("cp.async.commit_group;" ::: "memory");
        compute(cc % N_STAGE);
    }

#pragma unroll
    for (int mt = 0; mt < 4; ++mt) {
#pragma unroll
        for (int rr = 0; rr < 2; ++rr) {
            const int r = bm + wm * 64 + mt * 16 + g + rr * 8;
            if (r < p.M) {
                const int cb = bn + wn * 32;
#pragma unroll
                for (int nt = 0; nt < 4; ++nt) {
                    const int c = nt * 8 + t4 * 2;
                    float ox = acc[mt][nt][rr * 2 + 0];
                    float oy = acc[mt][nt][rr * 2 + 1];
                    if (p.add) {
                        __half2 av = *(const __half2*)(p.add + (size_t)r * p.N + cb + c);
                        float2 af = __half22float2(av);
                        ox += af.x; oy += af.y;
                    }
                    if (p.bias) {
                        ox = fmaxf(ox + p.bias[cb + c], 0.f);
                        oy = fmaxf(oy + p.bias[cb + c + 1], 0.f);
                    }
                    if (p.out_half) {
                        *(__half2*)((__half*)p.out + (size_t)r * p.N + cb + c) =
                            __floats2half2_rn(ox, oy);
                    } else {
                        *(float2*)((float*)p.out + (size_t)r * p.N + cb + c) =
                            make_float2(ox, oy);
                    }
                }
            }
        }
    }
}

// ---------------- launch (single stream, batched kernels) --------------------
extern "C" void kernel_launch(void* const* d_in, const int* in_sizes, int n_in,
                              void* d_out, int out_size) {
    const float* x_user = (const float*)d_in[0];
    const float* x_biz  = (const float*)d_in[1];
    const int* e_src = (const int*)d_in[2];
    const int* e_dst = (const int*)d_in[3];
    const float* b1_ub   = (const float*)d_in[6];
    const float* b1_bu   = (const float*)d_in[9];
    const float* b2_ub   = (const float*)d_in[12];
    const float* b2_bu   = (const float*)d_in[15];

    float* o_user = (float*)d_out;
    float* o_biz  = (float*)d_out + (size_t)N_USER * D_OUT;

    __half *xh_u, *xh_b, *mean_b1, *mean_u1, *h_biz, *h_user, *mean_b2, *y, *mean_y, *wt;
    float *inv_b, *inv_u;
    int *cnt_u, *cnt_b, *off_u, *off_b, *cur_u, *cur_b, *adj_u, *adj_b, *bsum;
    cudaGetSymbolAddress((void**)&xh_u,    g_xh_user);
    cudaGetSymbolAddress((void**)&xh_b,    g_xh_biz);
    cudaGetSymbolAddress((void**)&mean_b1, g_mean_b1);
    cudaGetSymbolAddress((void**)&mean_u1, g_mean_u1);
    cudaGetSymbolAddress((void**)&h_biz,   g_h_biz);
    cudaGetSymbolAddress((void**)&h_user,  g_h_user);
    cudaGetSymbolAddress((void**)&mean_b2, g_mean_b2);
    cudaGetSymbolAddress((void**)&y,       g_y);
    cudaGetSymbolAddress((void**)&mean_y,  g_mean_y);
    cudaGetSymbolAddress((void**)&wt,      g_wt);
    cudaGetSymbolAddress((void**)&inv_b,   g_inv_biz);
    cudaGetSymbolAddress((void**)&inv_u,   g_inv_user);
    cudaGetSymbolAddress((void**)&cnt_u,   g_cnt_user);
    cudaGetSymbolAddress((void**)&cnt_b,   g_cnt_biz);
    cudaGetSymbolAddress((void**)&off_u,   g_off_user);
    cudaGetSymbolAddress((void**)&off_b,   g_off_biz);
    cudaGetSymbolAddress((void**)&cur_u,   g_cur_user);
    cudaGetSymbolAddress((void**)&cur_b,   g_cur_biz);
    cudaGetSymbolAddress((void**)&adj_u,   g_adj_user);
    cudaGetSymbolAddress((void**)&adj_b,   g_adj_biz);
    cudaGetSymbolAddress((void**)&bsum,    g_bsum);

    cudaGetLastError();
    cudaFuncSetAttribute(sage_mma_batched,
                         cudaFuncAttributeMaxDynamicSharedMemorySize, SMEM_BYTES);

    // (1) prep: fp16 round + zero counters
    {
        int total = N_USER * D_IN / 4 + N_BIZ * D_IN / 4;
        prep_kernel<<<(total + 255) / 256, 256>>>((const float4*)x_user,
            (const float4*)x_biz, (__half2*)xh_u, (__half2*)xh_b, cnt_u, cnt_b);
    }
    // (2) all weight transposes in one launch
    {
        TransProbs tp;
        tp.W[0] = (const float*)d_in[4];  tp.W[1] = (const float*)d_in[5];
        tp.W[2] = (const float*)d_in[7];  tp.W[3] = (const float*)d_in[8];
        tp.W[4] = (const float*)d_in[10]; tp.W[5] = (const float*)d_in[11];
        tp.W[6] = (const float*)d_in[13]; tp.W[7] = (const float*)d_in[14];
        dim3 blk(32, 8);
        dim3 grd(16, 16, 8);
        transpose_all_kernel<<<grd, blk>>>(tp, wt);
    }
    // (3-7) CSR build
    hist_kernel<<<(NEDGE + 255) / 256, 256>>>(e_src, e_dst, cnt_u, cnt_b, NEDGE);
    scanA_kernel<<<NBLK_TOT, 1024>>>(cnt_u, cnt_b, bsum);
    scanB_kernel<<<1, 32>>>(bsum);
    scanC_kernel<<<NBLK_TOT, 1024>>>(cnt_u, cnt_b, bsum, off_u, cur_u, inv_u,
                                     off_b, cur_b, inv_b);
    fill_kernel<<<(NEDGE + 255) / 256, 256>>>(e_src, e_dst, cur_u, cur_b,
                                              adj_u, adj_b, NEDGE);

    // (8) L1 gathers fused: mean_b1 (biz<-user feats) + mean_u1 (user<-biz feats)
    {
        GatherProb p0{(const uint4*)xh_u, off_b, adj_b, inv_b, (uint4*)mean_b1,
                      D_IN / 8, N_BIZ, (N_BIZ + 1) / 2};
        GatherProb p1{(const uint4*)xh_b, off_u, adj_u, inv_u, (uint4*)mean_u1,
                      D_IN / 8, N_USER, (N_USER + 1) / 2};
        gather2_kernel<<<p0.nblk + p1.nblk, 64>>>(p0, p1);
    }

    // (9) L1 GEMMs batched: h_biz + h_user
    {
        GProb q0{mean_b1, xh_b, wt + 0 * 131072, wt + 1 * 131072, b1_ub, nullptr,
                 h_biz, N_BIZ, D_IN, D_H, 2, 1, (N_BIZ + 127) / 128};
        GProb q1{mean_u1, xh_u, wt + 2 * 131072, wt + 3 * 131072, b1_bu, nullptr,
                 h_user, N_USER, D_IN, D_H, 2, 1, (N_USER + 127) / 128};
        dim3 grd(D_H / 128, (N_USER + 127) / 128, 2);
        sage_mma_batched<<<grd, 256, SMEM_BYTES>>>(q0, q1);
    }

    // (10) y = h_biz @ W2_l_bu (fp16, M=50k) — single problem
    {
        GProb q0{h_biz, h_biz, wt + 6 * 131072, wt + 6 * 131072, nullptr, nullptr,
                 y, N_BIZ, D_H, D_OUT, 1, 1, (N_BIZ + 127) / 128};
        dim3 grd(D_OUT / 128, (N_BIZ + 127) / 128, 1);
        sage_mma_batched<<<grd, 256, SMEM_BYTES>>>(q0, q0);
    }

    // (11) L2 gathers fused: mean_b2 (from h_user, d8=64) + mean_y (from y, d8=32)
    {
        GatherProb p0{(const uint4*)h_user, off_b, adj_b, inv_b, (uint4*)mean_b2,
                      D_H / 8, N_BIZ, N_BIZ};
        GatherProb p1{(const uint4*)y, off_u, adj_u, inv_u, (uint4*)mean_y,
                      D_OUT / 8, N_USER, (N_USER + 1) / 2};
        gather2_kernel<<<p0.nblk + p1.nblk, 64>>>(p0, p1);
    }

    // (12) final GEMMs batched: o_biz + o_user
    {
        GProb q0{mean_b2, h_biz, wt + 4 * 131072, wt + 5 * 131072, b2_ub, nullptr,
                 o_biz, N_BIZ, D_H, D_OUT, 2, 0, (N_BIZ + 127) / 128};
        GProb q1{h_user, h_user, wt + 7 * 131072, wt + 7 * 131072, b2_bu, mean_y,
                 o_user, N_USER, D_H, D_OUT, 1, 0, (N_USER + 127) / 128};
        dim3 grd(D_OUT / 128, (N_USER + 127) / 128, 2);
        sage_mma_batched<<<grd, 256, SMEM_BYTES>>>(q0, q1);
    }
}